// round 11
// baseline (speedup 1.0000x reference)
#include <cuda_runtime.h>
#include <math.h>

#define Bq 128
#define Sq 512
#define Tq 16
#define Eq 32
#define Hq 128
#define G3 192
#define GD 384
#define XD 160
#define Vq 32000
#define NSTEP 15

// ---------------- device scratch (static globals; no runtime alloc) -------
static __device__ float g_gi_f[(size_t)Sq * Bq * G3];   // [t][b][192]
static __device__ float g_gi_b[(size_t)Sq * Bq * G3];   // [t][b][192]
static __device__ float g_enc [(size_t)Bq * Sq * Hq];   // raw encoder outputs [b][s][h]
static __device__ float g_encg[(size_t)Bq * Sq * Hq];   // gated encoder outputs
static __device__ float g_hdec[Bq * Hq];                // decoder hidden
static __device__ float g_c2  [Bq * Hq];                // sn@W2^T + b1 + b2
static __device__ float g_xdec[Bq * XD];                // [ctx(128) | emb(32)] per b

__device__ __forceinline__ float sigf(float x) { return 1.f / (1.f + __expf(-x)); }

// ---------------- generic 64(M) x 128(N) fp32 tile body, BK=32 -----------
#define WIDE_PROLOG()                                                          \
    __shared__ float As[32][68];                                               \
    __shared__ float Bs[32][136];                                              \
    float acc[4][8];                                                           \
    _Pragma("unroll") for (int i = 0; i < 4; i++)                              \
        _Pragma("unroll") for (int j = 0; j < 8; j++) acc[i][j] = 0.f;         \
    const int tid = threadIdx.x;                                               \
    const int tx = tid & 15, ty = tid >> 4;

#define WIDE_KSTEP(AROW, BROW, K0)                                             \
    {                                                                          \
        const int k0 = (K0);                                                   \
        _Pragma("unroll") for (int jj = 0; jj < 2; jj++) {                     \
            int fid = tid + jj * 256;                                          \
            int m = fid >> 3, kq = fid & 7;                                    \
            const float* ap = (AROW);                                          \
            float4 v = *(const float4*)(ap + k0 + kq * 4);                     \
            As[kq*4+0][m] = v.x; As[kq*4+1][m] = v.y;                          \
            As[kq*4+2][m] = v.z; As[kq*4+3][m] = v.w;                          \
        }                                                                      \
        _Pragma("unroll") for (int jj = 0; jj < 4; jj++) {                     \
            int fid = tid + jj * 256;                                          \
            int n = fid >> 3, kq = fid & 7;                                    \
            const float* bp = (BROW);                                          \
            float4 v = *(const float4*)(bp + k0 + kq * 4);                     \
            Bs[kq*4+0][n] = v.x; Bs[kq*4+1][n] = v.y;                          \
            Bs[kq*4+2][n] = v.z; Bs[kq*4+3][n] = v.w;                          \
        }                                                                      \
        __syncthreads();                                                       \
        _Pragma("unroll") for (int k = 0; k < 32; k++) {                       \
            float4 a  = *(const float4*)&As[k][ty * 4];                        \
            float4 bl = *(const float4*)&Bs[k][tx * 8];                        \
            float4 bh = *(const float4*)&Bs[k][tx * 8 + 4];                    \
            float av[4] = {a.x, a.y, a.z, a.w};                                \
            float bv[8] = {bl.x, bl.y, bl.z, bl.w, bh.x, bh.y, bh.z, bh.w};    \
            _Pragma("unroll") for (int i = 0; i < 4; i++)                      \
                _Pragma("unroll") for (int j = 0; j < 8; j++)                  \
                    acc[i][j] += av[i] * bv[j];                                \
        }                                                                      \
        __syncthreads();                                                       \
    }

// ================= K1: embedding gather + input projection ================
// gi_f / gi_b for all (t,b).  M = S*B = 65536 (row r = t*B+b), N = 384, K = 32
__global__ __launch_bounds__(256) void k_gi(
    const int* __restrict__ inputs, const float* __restrict__ emb,
    const float* __restrict__ Wf, const float* __restrict__ Wb,
    const float* __restrict__ bf, const float* __restrict__ bb)
{
    __shared__ int tok[64];
    const int m0 = blockIdx.y * 64;
    const int n0 = blockIdx.x * 128;
    if (threadIdx.x < 64) {
        int r = m0 + threadIdx.x;
        tok[threadIdx.x] = inputs[(r & (Bq - 1)) * Sq + (r >> 7)];
    }
    __syncthreads();
    WIDE_PROLOG();
    WIDE_KSTEP(emb + (size_t)tok[m] * Eq,
               ((n0 + n) < G3) ? (Wf + (n0 + n) * Eq)
                               : (Wb + (n0 + n - G3) * Eq),
               0);
    #pragma unroll
    for (int i = 0; i < 4; i++) {
        int r = m0 + ty * 4 + i;
        #pragma unroll
        for (int j = 0; j < 8; j++) {
            int col = n0 + tx * 8 + j;
            float v = acc[i][j];
            if (col < G3) g_gi_f[(size_t)r * G3 + col] = v + bf[col];
            else          g_gi_b[(size_t)r * G3 + (col - G3)] = v + bb[col - G3];
        }
    }
}

// ==================== K2: encoder recurrence (both dirs) ==================
__global__ __launch_bounds__(192) void k_enc(
    const float* __restrict__ Whf, const float* __restrict__ Whb,
    const float* __restrict__ bhf, const float* __restrict__ bhb)
{
    const int b   = blockIdx.x & 127;
    const int dir = blockIdx.x >> 7;
    const int g   = threadIdx.x;
    const float* Wh = dir ? Whb : Whf;
    const float* bh = dir ? bhb : bhf;
    const float* gi = dir ? g_gi_b : g_gi_f;

    __shared__ float h_sh[64];
    __shared__ float gh_sh[G3];
    __shared__ float gi_sh[G3];

    float w[64];
    #pragma unroll
    for (int k = 0; k < 64; k++) w[k] = Wh[g * 64 + k];
    const float bhg = bh[g];
    if (g < 64) h_sh[g] = 0.f;
    __syncthreads();

    int t = dir ? (Sq - 1) : 0;
    const int dt = dir ? -1 : 1;
    float gcur = gi[((size_t)t * Bq + b) * G3 + g];

    for (int it = 0; it < Sq; it++, t += dt) {
        float gnext = 0.f;
        if (it + 1 < Sq) gnext = gi[((size_t)(t + dt) * Bq + b) * G3 + g];
        float a0 = bhg, a1 = 0.f, a2 = 0.f, a3 = 0.f;
        #pragma unroll
        for (int k = 0; k < 64; k += 4) {
            a0 += h_sh[k + 0] * w[k + 0];
            a1 += h_sh[k + 1] * w[k + 1];
            a2 += h_sh[k + 2] * w[k + 2];
            a3 += h_sh[k + 3] * w[k + 3];
        }
        gh_sh[g] = (a0 + a1) + (a2 + a3);
        gi_sh[g] = gcur;
        __syncthreads();
        if (g < 64) {
            float r  = sigf(gi_sh[g] + gh_sh[g]);
            float z  = sigf(gi_sh[64 + g] + gh_sh[64 + g]);
            float n  = tanhf(gi_sh[128 + g] + r * gh_sh[128 + g]);
            float hn = (1.f - z) * n + z * h_sh[g];
            h_sh[g] = hn;
            g_enc[((size_t)b * Sq + t) * Hq + dir * 64 + g] = hn;
        }
        __syncthreads();
        gcur = gnext;
    }
    if (g < 64) g_hdec[b * Hq + dir * 64 + g] = h_sh[g];
}

// ========= K3: c2[b][h] = sn@W2^T + b1 + b2 ================================
__global__ __launch_bounds__(128) void k_c2(
    const float* __restrict__ W2, const float* __restrict__ b1,
    const float* __restrict__ b2)
{
    const int b = blockIdx.x, h = threadIdx.x;
    __shared__ float sn[128];
    sn[h] = g_hdec[b * 128 + h];
    __syncthreads();
    float a = b1[h] + b2[h];
    const float* wr = W2 + h * 128;
    #pragma unroll 8
    for (int k = 0; k < 128; k++) a += sn[k] * wr[k];
    g_c2[b * 128 + h] = a;
}

// ===== K4: sGate GEMM + gating =============================================
// M = B*S = 65536 (row r = b*S+s), N = 128, K = 128
__global__ __launch_bounds__(256) void k_gate(const float* __restrict__ W1)
{
    const int m0 = blockIdx.y * 64;
    const int n0 = 0;
    WIDE_PROLOG();
    for (int kk = 0; kk < 128; kk += 32) {
        WIDE_KSTEP(g_enc + (size_t)(m0 + m) * Hq,
                   W1 + (n0 + n) * 128,
                   kk);
    }
    #pragma unroll
    for (int i = 0; i < 4; i++) {
        int r = m0 + ty * 4 + i;
        int bb2 = r >> 9;  // b = r / S
        #pragma unroll
        for (int j = 0; j < 8; j++) {
            int col = n0 + tx * 8 + j;
            float u   = acc[i][j] + g_c2[bb2 * 128 + col];
            float raw = g_enc[(size_t)r * Hq + col];
            g_encg[(size_t)r * Hq + col] = raw * sigf(u);
        }
    }
}

// ====== K5: attention (warp-shuffle reductions) + embed concat ============
__global__ __launch_bounds__(256) void k_attn2(
    const float* __restrict__ emb, const int* __restrict__ targets, int step)
{
    const int b = blockIdx.x, tid = threadIdx.x;
    const int lane = tid & 31, wrp = tid >> 5;   // 8 warps
    __shared__ float hsh[128];
    __shared__ float sc[512];
    __shared__ float wred[8];
    __shared__ float red[256];
    if (tid < 128) hsh[tid] = g_hdec[b * 128 + tid];
    __syncthreads();

    const float* eb = g_encg + (size_t)b * Sq * Hq;
    float a0 = 0.f, a1 = 0.f;
    {
        const float4* r0 = (const float4*)(eb + (size_t)tid * 128);
        const float4* r1 = (const float4*)(eb + (size_t)(tid + 256) * 128);
        #pragma unroll
        for (int q = 0; q < 32; q++) {
            float4 v0 = r0[q], v1 = r1[q];
            float h0 = hsh[q*4], h1 = hsh[q*4+1], h2 = hsh[q*4+2], h3 = hsh[q*4+3];
            a0 += v0.x*h0 + v0.y*h1 + v0.z*h2 + v0.w*h3;
            a1 += v1.x*h0 + v1.y*h1 + v1.z*h2 + v1.w*h3;
        }
    }
    float m = fmaxf(a0, a1);
    #pragma unroll
    for (int o = 16; o > 0; o >>= 1) m = fmaxf(m, __shfl_xor_sync(0xffffffffu, m, o));
    if (lane == 0) wred[wrp] = m;
    __syncthreads();
    float mx = wred[0];
    #pragma unroll
    for (int i = 1; i < 8; i++) mx = fmaxf(mx, wred[i]);

    float e0 = __expf(a0 - mx), e1 = __expf(a1 - mx);
    sc[tid] = e0; sc[tid + 256] = e1;
    float s = e0 + e1;
    #pragma unroll
    for (int o = 16; o > 0; o >>= 1) s += __shfl_xor_sync(0xffffffffu, s, o);
    __syncthreads();
    if (lane == 0) wred[wrp] = s;
    __syncthreads();
    float tot = 0.f;
    #pragma unroll
    for (int i = 0; i < 8; i++) tot += wred[i];
    float inv = 1.f / tot;

    // context: thread = (half, d); each half sums 256 s-values
    const int d = tid & 127, half = tid >> 7;
    float c = 0.f;
    const int s0 = half * 256;
    #pragma unroll 4
    for (int s2 = s0; s2 < s0 + 256; s2++) c += sc[s2] * eb[(size_t)s2 * 128 + d];
    red[tid] = c;
    __syncthreads();
    if (half == 0) {
        g_xdec[b * XD + d] = (red[d] + red[128 + d]) * inv;
    } else if (d < Eq) {
        int wrd = targets[b * Tq + step];
        g_xdec[b * XD + 128 + d] = emb[(size_t)wrd * Eq + d];
    }
}

// ====== K6: decoder GRU (one CTA per b, warp-per-row dots) ================
// gi[g] = b_ih_d[g] + sum_{k<160} W_ih_d[g,k] * x[k]   (x = [ctx(128)|emb(32)])
// gh[g] = b_hh_d[g] + sum_{k<128} W_hh_d[g,k] * h[k]
__global__ __launch_bounds__(384) void k_dgru(
    const float* __restrict__ Wihd, const float* __restrict__ Whhd,
    const float* __restrict__ bihd, const float* __restrict__ bhhd)
{
    const int b = blockIdx.x;
    const int tid = threadIdx.x;
    const int lane = tid & 31, wrp = tid >> 5;   // 12 warps
    __shared__ float x_sh[XD];
    __shared__ float h_sh[128];
    __shared__ float gis[GD];
    __shared__ float ghs[GD];
    if (tid < XD) x_sh[tid] = g_xdec[b * XD + tid];
    if (tid >= 256) h_sh[tid - 256] = g_hdec[b * 128 + (tid - 256)];
    __syncthreads();

    for (int i = 0; i < 32; i++) {
        const int row = wrp * 32 + i;
        const float* wi = Wihd + (size_t)row * XD;
        const float* wh = Whhd + (size_t)row * 128;
        float a = 0.f, c = 0.f;
        #pragma unroll
        for (int q = 0; q < 5; q++) a += wi[lane + q * 32] * x_sh[lane + q * 32];
        #pragma unroll
        for (int q = 0; q < 4; q++) c += wh[lane + q * 32] * h_sh[lane + q * 32];
        #pragma unroll
        for (int o = 16; o > 0; o >>= 1) {
            a += __shfl_down_sync(0xffffffffu, a, o);
            c += __shfl_down_sync(0xffffffffu, c, o);
        }
        if (lane == 0) { gis[row] = a; ghs[row] = c; }
    }
    __syncthreads();

    if (tid < 128) {
        float gi0 = gis[tid]        + bihd[tid];
        float gh0 = ghs[tid]        + bhhd[tid];
        float gi1 = gis[128 + tid]  + bihd[128 + tid];
        float gh1 = ghs[128 + tid]  + bhhd[128 + tid];
        float gi2 = gis[256 + tid]  + bihd[256 + tid];
        float gh2 = ghs[256 + tid]  + bhhd[256 + tid];
        float r = sigf(gi0 + gh0);
        float z = sigf(gi1 + gh1);
        float n = tanhf(gi2 + r * gh2);
        g_hdec[b * 128 + tid] = (1.f - z) * n + z * h_sh[tid];
    }
}

// ===================== K8: logits GEMM (dominant cost) ====================
// M = 128 (b), N = 32000 (v), K = 128;  grid (250 ntiles, 2 mtiles)
__global__ __launch_bounds__(256) void k_logits(
    const float* __restrict__ Wout, const float* __restrict__ bout,
    float* __restrict__ out, int step)
{
    const int m0 = blockIdx.y * 64;
    const int n0 = blockIdx.x * 128;
    WIDE_PROLOG();
    for (int kk = 0; kk < 128; kk += 32) {
        WIDE_KSTEP(g_hdec + (m0 + m) * 128,
                   Wout + (size_t)(n0 + n) * 128,
                   kk);
    }
    #pragma unroll
    for (int i = 0; i < 4; i++) {
        int bb2 = m0 + ty * 4 + i;
        size_t base = ((size_t)bb2 * NSTEP + step) * Vq;
        #pragma unroll
        for (int j = 0; j < 8; j++) {
            int v = n0 + tx * 8 + j;
            out[base + v] = acc[i][j] + bout[v];
        }
    }
}

// ============ trap sentinel (should never fire now) =======================
__global__ void k_trap() { __trap(); }

// ============================== launcher ==================================
extern "C" void kernel_launch(void* const* d_in, const int* in_sizes, int n_in,
                              void* d_out, int out_size)
{
    // Measured ground-truth signature (R8 HXDBG dump): dict-insertion order,
    // element counts, E = 32.
    static const int SZ[21] = {65536, 2048, 1024000, 6144, 12288, 192, 192,
                               6144, 12288, 192, 192, 16384, 128, 16384, 128,
                               61440, 49152, 384, 384, 4096000, 32000};
    bool ok = (n_in == 21);
    if (ok) for (int i = 0; i < 21; i++) if (in_sizes[i] != SZ[i]) { ok = false; break; }
    if (!ok) { k_trap<<<1, 1>>>(); return; }

    const int*   inputs  = (const int*)  d_in[0];
    const int*   targets = (const int*)  d_in[1];
    const float* emb     = (const float*)d_in[2];
    const float* W_ih_f  = (const float*)d_in[3];
    const float* W_hh_f  = (const float*)d_in[4];
    const float* b_ih_f  = (const float*)d_in[5];
    const float* b_hh_f  = (const float*)d_in[6];
    const float* W_ih_b  = (const float*)d_in[7];
    const float* W_hh_b  = (const float*)d_in[8];
    const float* b_ih_b  = (const float*)d_in[9];
    const float* b_hh_b  = (const float*)d_in[10];
    const float* W1      = (const float*)d_in[11];
    const float* b1      = (const float*)d_in[12];
    const float* W2      = (const float*)d_in[13];
    const float* b2      = (const float*)d_in[14];
    const float* W_ih_d  = (const float*)d_in[15];
    const float* W_hh_d  = (const float*)d_in[16];
    const float* b_ih_d  = (const float*)d_in[17];
    const float* b_hh_d  = (const float*)d_in[18];
    const float* W_out   = (const float*)d_in[19];
    const float* b_out   = (const float*)d_in[20];
    float* out = (float*)d_out;

    k_gi <<<dim3(3, 1024), 256>>>(inputs, emb, W_ih_f, W_ih_b, b_ih_f, b_ih_b);
    k_enc<<<256, 192>>>(W_hh_f, W_hh_b, b_hh_f, b_hh_b);
    k_c2  <<<128, 128>>>(W2, b1, b2);
    k_gate<<<dim3(1, 1024), 256>>>(W1);
    for (int step = 0; step < NSTEP; step++) {
        k_attn2 <<<128, 256>>>(emb, targets, step);
        k_dgru  <<<128, 384>>>(W_ih_d, W_hh_d, b_ih_d, b_hh_d);
        k_logits<<<dim3(250, 2), 256>>>(W_out, b_out, out, step);
    }
}

// round 12
// speedup vs baseline: 1.2184x; 1.2184x over previous
#include <cuda_runtime.h>
#include <math.h>

#define Bq 128
#define Sq 512
#define Tq 16
#define Eq 32
#define Hq 128
#define G3 192
#define GD 384
#define XD 160
#define Vq 32000
#define NSTEP 15

// ---------------- device scratch (static globals; no runtime alloc) -------
static __device__ float g_gi_f[(size_t)Sq * Bq * G3];   // [t][b][192]
static __device__ float g_gi_b[(size_t)Sq * Bq * G3];   // [t][b][192]
static __device__ float g_enc [(size_t)Bq * Sq * Hq];   // raw encoder outputs [b][s][h]
static __device__ float g_encg[(size_t)Bq * Sq * Hq];   // gated encoder outputs
static __device__ float g_hdec[Bq * Hq];                // decoder initial hidden (sn)
static __device__ float g_c2  [Bq * Hq];                // sn@W2^T + b1 + b2
static __device__ float g_hall[(size_t)NSTEP * Bq * Hq];// h after each decoder step

__device__ __forceinline__ float sigf(float x) { return 1.f / (1.f + __expf(-x)); }

// ============ 128(M) x 128(N) fp32 tile, 256 thr, 8x8 micro (quadrants) ===
// Thread (tx,ty) owns rows {ty*4..+3, 64+ty*4..+3} x cols {tx*4..+3, 64+tx*4..+3}.
// Compute-phase LDS.128: B addresses tx*4 cover all 32 banks (16 float4 = 2
// clean phases); A addresses broadcast. 64 FMA per 64 smem bytes.
#define G128_PROLOG()                                                          \
    __shared__ float As[32][132];                                              \
    __shared__ float Bs[32][132];                                              \
    float acc[8][8];                                                           \
    _Pragma("unroll") for (int i = 0; i < 8; i++)                              \
        _Pragma("unroll") for (int j = 0; j < 8; j++) acc[i][j] = 0.f;         \
    const int tid = threadIdx.x;                                               \
    const int tx = tid & 15, ty = tid >> 4;

#define G128_KSTEP(AROW, BROW, K0)                                             \
    {                                                                          \
        const int k0 = (K0);                                                   \
        _Pragma("unroll") for (int jj = 0; jj < 4; jj++) {                     \
            int fid = tid + jj * 256;                                          \
            int m = fid >> 3, kq = fid & 7;                                    \
            const float* ap = (AROW);                                          \
            float4 v = *(const float4*)(ap + k0 + kq * 4);                     \
            As[kq*4+0][m] = v.x; As[kq*4+1][m] = v.y;                          \
            As[kq*4+2][m] = v.z; As[kq*4+3][m] = v.w;                          \
        }                                                                      \
        _Pragma("unroll") for (int jj = 0; jj < 4; jj++) {                     \
            int fid = tid + jj * 256;                                          \
            int n = fid >> 3, kq = fid & 7;                                    \
            const float* bp = (BROW);                                          \
            float4 v = *(const float4*)(bp + k0 + kq * 4);                     \
            Bs[kq*4+0][n] = v.x; Bs[kq*4+1][n] = v.y;                          \
            Bs[kq*4+2][n] = v.z; Bs[kq*4+3][n] = v.w;                          \
        }                                                                      \
        __syncthreads();                                                       \
        _Pragma("unroll") for (int k = 0; k < 32; k++) {                       \
            float4 a0 = *(const float4*)&As[k][ty * 4];                        \
            float4 a1 = *(const float4*)&As[k][64 + ty * 4];                   \
            float4 b0 = *(const float4*)&Bs[k][tx * 4];                        \
            float4 b1 = *(const float4*)&Bs[k][64 + tx * 4];                   \
            float av[8] = {a0.x,a0.y,a0.z,a0.w, a1.x,a1.y,a1.z,a1.w};          \
            float bv[8] = {b0.x,b0.y,b0.z,b0.w, b1.x,b1.y,b1.z,b1.w};          \
            _Pragma("unroll") for (int i = 0; i < 8; i++)                      \
                _Pragma("unroll") for (int j = 0; j < 8; j++)                  \
                    acc[i][j] += av[i] * bv[j];                                \
        }                                                                      \
        __syncthreads();                                                       \
    }

#define QROW(q) (((q) < 4) ? (ty * 4 + (q)) : (60 + ty * 4 + (q)))
#define QCOL(q) (((q) < 4) ? (tx * 4 + (q)) : (60 + tx * 4 + (q)))

// ================= K1: embedding gather + input projection ================
// M = S*B = 65536 (row r = t*B+b), N = 384, K = 32; grid (3, 512)
__global__ __launch_bounds__(256, 2) void k_gi(
    const int* __restrict__ inputs, const float* __restrict__ emb,
    const float* __restrict__ Wf, const float* __restrict__ Wb,
    const float* __restrict__ bf, const float* __restrict__ bb)
{
    __shared__ int tok[128];
    const int m0 = blockIdx.y * 128;
    const int n0 = blockIdx.x * 128;
    if (threadIdx.x < 128) {
        int r = m0 + threadIdx.x;
        tok[threadIdx.x] = inputs[(r & (Bq - 1)) * Sq + (r >> 7)];
    }
    __syncthreads();
    G128_PROLOG();
    G128_KSTEP(emb + (size_t)tok[m] * Eq,
               ((n0 + n) < G3) ? (Wf + (n0 + n) * Eq)
                               : (Wb + (n0 + n - G3) * Eq),
               0);
    #pragma unroll
    for (int i = 0; i < 8; i++) {
        int r = m0 + QROW(i);
        #pragma unroll
        for (int j = 0; j < 8; j++) {
            int col = n0 + QCOL(j);
            float v = acc[i][j];
            if (col < G3) g_gi_f[(size_t)r * G3 + col] = v + bf[col];
            else          g_gi_b[(size_t)r * G3 + (col - G3)] = v + bb[col - G3];
        }
    }
}

// ==================== K2: encoder recurrence (both dirs) ==================
__global__ __launch_bounds__(192) void k_enc(
    const float* __restrict__ Whf, const float* __restrict__ Whb,
    const float* __restrict__ bhf, const float* __restrict__ bhb)
{
    const int b   = blockIdx.x & 127;
    const int dir = blockIdx.x >> 7;
    const int g   = threadIdx.x;
    const float* Wh = dir ? Whb : Whf;
    const float* bh = dir ? bhb : bhf;
    const float* gi = dir ? g_gi_b : g_gi_f;

    __shared__ float h_sh[64];
    __shared__ float gh_sh[G3];
    __shared__ float gi_sh[G3];

    float w[64];
    #pragma unroll
    for (int k = 0; k < 64; k++) w[k] = Wh[g * 64 + k];
    const float bhg = bh[g];
    if (g < 64) h_sh[g] = 0.f;
    __syncthreads();

    int t = dir ? (Sq - 1) : 0;
    const int dt = dir ? -1 : 1;
    float gcur = gi[((size_t)t * Bq + b) * G3 + g];

    for (int it = 0; it < Sq; it++, t += dt) {
        float gnext = 0.f;
        if (it + 1 < Sq) gnext = gi[((size_t)(t + dt) * Bq + b) * G3 + g];
        float a0 = bhg, a1 = 0.f, a2 = 0.f, a3 = 0.f;
        #pragma unroll
        for (int k = 0; k < 64; k += 4) {
            a0 += h_sh[k + 0] * w[k + 0];
            a1 += h_sh[k + 1] * w[k + 1];
            a2 += h_sh[k + 2] * w[k + 2];
            a3 += h_sh[k + 3] * w[k + 3];
        }
        gh_sh[g] = (a0 + a1) + (a2 + a3);
        gi_sh[g] = gcur;
        __syncthreads();
        if (g < 64) {
            float r  = sigf(gi_sh[g] + gh_sh[g]);
            float z  = sigf(gi_sh[64 + g] + gh_sh[64 + g]);
            float n  = tanhf(gi_sh[128 + g] + r * gh_sh[128 + g]);
            float hn = (1.f - z) * n + z * h_sh[g];
            h_sh[g] = hn;
            g_enc[((size_t)b * Sq + t) * Hq + dir * 64 + g] = hn;
        }
        __syncthreads();
        gcur = gnext;
    }
    if (g < 64) g_hdec[b * Hq + dir * 64 + g] = h_sh[g];
}

// ========= K3: c2[b][h] = sn@W2^T + b1 + b2 ================================
__global__ __launch_bounds__(128) void k_c2(
    const float* __restrict__ W2, const float* __restrict__ b1,
    const float* __restrict__ b2)
{
    const int b = blockIdx.x, h = threadIdx.x;
    __shared__ float sn[128];
    sn[h] = g_hdec[b * 128 + h];
    __syncthreads();
    float a = b1[h] + b2[h];
    const float* wr = W2 + h * 128;
    #pragma unroll 8
    for (int k = 0; k < 128; k++) a += sn[k] * wr[k];
    g_c2[b * 128 + h] = a;
}

// ===== K4: sGate GEMM + gating =============================================
// M = B*S = 65536 (row r = b*S+s), N = 128, K = 128; grid (1, 512)
__global__ __launch_bounds__(256, 2) void k_gate(const float* __restrict__ W1)
{
    const int m0 = blockIdx.y * 128;
    G128_PROLOG();
    for (int kk = 0; kk < 128; kk += 32) {
        G128_KSTEP(g_enc + (size_t)(m0 + m) * Hq,
                   W1 + n * 128,
                   kk);
    }
    #pragma unroll
    for (int i = 0; i < 8; i++) {
        int r = m0 + QROW(i);
        int bb2 = r >> 9;  // b = r / S
        #pragma unroll
        for (int j = 0; j < 8; j++) {
            int col = QCOL(j);
            float u   = acc[i][j] + g_c2[bb2 * 128 + col];
            float raw = g_enc[(size_t)r * Hq + col];
            g_encg[(size_t)r * Hq + col] = raw * sigf(u);
        }
    }
}

// ====== K5: persistent decoder: 15 steps of attention+GRU per CTA (= b) ===
__global__ __launch_bounds__(256) void k_dec_all(
    const float* __restrict__ emb, const int* __restrict__ targets,
    const float* __restrict__ Wihd, const float* __restrict__ Whhd,
    const float* __restrict__ bihd, const float* __restrict__ bhhd)
{
    const int b = blockIdx.x;
    const int tid = threadIdx.x;
    const int lane = tid & 31, wrp = tid >> 5;   // 8 warps
    __shared__ float hsh[128];
    __shared__ float sc[512];
    __shared__ float wred[8];
    __shared__ float red[256];
    __shared__ float xe[XD];
    __shared__ float gis[GD];
    __shared__ float ghs[GD];

    if (tid < 128) hsh[tid] = g_hdec[b * 128 + tid];
    __syncthreads();

    const float* eb = g_encg + (size_t)b * Sq * Hq;

    for (int step = 0; step < NSTEP; step++) {
        // ---- scores: rows tid and tid+256 ----
        float a0 = 0.f, a1 = 0.f;
        {
            const float4* r0 = (const float4*)(eb + (size_t)tid * 128);
            const float4* r1 = (const float4*)(eb + (size_t)(tid + 256) * 128);
            #pragma unroll
            for (int q = 0; q < 32; q++) {
                float4 v0 = r0[q], v1 = r1[q];
                float h0 = hsh[q*4], h1 = hsh[q*4+1], h2 = hsh[q*4+2], h3 = hsh[q*4+3];
                a0 += v0.x*h0 + v0.y*h1 + v0.z*h2 + v0.w*h3;
                a1 += v1.x*h0 + v1.y*h1 + v1.z*h2 + v1.w*h3;
            }
        }
        // ---- softmax: max ----
        float m = fmaxf(a0, a1);
        #pragma unroll
        for (int o = 16; o > 0; o >>= 1) m = fmaxf(m, __shfl_xor_sync(0xffffffffu, m, o));
        if (lane == 0) wred[wrp] = m;
        __syncthreads();
        float mx = wred[0];
        #pragma unroll
        for (int i = 1; i < 8; i++) mx = fmaxf(mx, wred[i]);

        float e0 = __expf(a0 - mx), e1 = __expf(a1 - mx);
        sc[tid] = e0; sc[tid + 256] = e1;
        float s = e0 + e1;
        #pragma unroll
        for (int o = 16; o > 0; o >>= 1) s += __shfl_xor_sync(0xffffffffu, s, o);
        __syncthreads();                       // wred(max) consumed by all
        if (lane == 0) wred[wrp] = s;
        __syncthreads();
        float tot = 0.f;
        #pragma unroll
        for (int i = 0; i < 8; i++) tot += wred[i];
        float inv = 1.f / tot;

        // ---- context: thread = (half, d) ----
        const int d = tid & 127, half = tid >> 7;
        float c = 0.f;
        const int s0 = half * 256;
        #pragma unroll 4
        for (int s2 = s0; s2 < s0 + 256; s2++) c += sc[s2] * eb[(size_t)s2 * 128 + d];
        red[tid] = c;
        __syncthreads();
        if (half == 0) {
            xe[d] = (red[d] + red[128 + d]) * inv;
        } else if (d < Eq) {
            int wrd = targets[b * Tq + step];
            xe[128 + d] = emb[(size_t)wrd * Eq + d];
        }
        __syncthreads();

        // ---- GRU: 8 warps x 48 gate rows, lane-strided dots ----
        for (int i = 0; i < 48; i++) {
            const int row = wrp * 48 + i;
            const float* wi = Wihd + (size_t)row * XD;
            const float* wh = Whhd + (size_t)row * 128;
            float a = 0.f, cc = 0.f;
            #pragma unroll
            for (int q = 0; q < 5; q++) a += wi[lane + q * 32] * xe[lane + q * 32];
            #pragma unroll
            for (int q = 0; q < 4; q++) cc += wh[lane + q * 32] * hsh[lane + q * 32];
            #pragma unroll
            for (int o = 16; o > 0; o >>= 1) {
                a  += __shfl_down_sync(0xffffffffu, a, o);
                cc += __shfl_down_sync(0xffffffffu, cc, o);
            }
            if (lane == 0) { gis[row] = a; ghs[row] = cc; }
        }
        __syncthreads();

        if (tid < 128) {
            float gi0 = gis[tid]       + bihd[tid];
            float gh0 = ghs[tid]       + bhhd[tid];
            float gi1 = gis[128 + tid] + bihd[128 + tid];
            float gh1 = ghs[128 + tid] + bhhd[128 + tid];
            float gi2 = gis[256 + tid] + bihd[256 + tid];
            float gh2 = ghs[256 + tid] + bhhd[256 + tid];
            float r = sigf(gi0 + gh0);
            float z = sigf(gi1 + gh1);
            float n = tanhf(gi2 + r * gh2);
            float hn = (1.f - z) * n + z * hsh[tid];
            hsh[tid] = hn;
            g_hall[((size_t)step * Bq + b) * Hq + tid] = hn;
        }
        __syncthreads();
    }
}

// ========== K6: batched logits GEMM: M = 15*128 = 1920, N = 32000 =========
// row r = step*B+b; out[b][step][v]; grid (250, 15)
__global__ __launch_bounds__(256, 2) void k_logits_all(
    const float* __restrict__ Wout, const float* __restrict__ bout,
    float* __restrict__ out)
{
    const int m0 = blockIdx.y * 128;
    const int n0 = blockIdx.x * 128;
    G128_PROLOG();
    for (int kk = 0; kk < 128; kk += 32) {
        G128_KSTEP(g_hall + (size_t)(m0 + m) * Hq,
                   Wout + (size_t)(n0 + n) * Hq,
                   kk);
    }
    #pragma unroll
    for (int i = 0; i < 8; i++) {
        int r = m0 + QROW(i);
        int step = r >> 7, b2 = r & 127;
        size_t base = ((size_t)b2 * NSTEP + step) * Vq + n0;
        #pragma unroll
        for (int jq = 0; jq < 2; jq++) {
            int col0 = jq ? (64 + tx * 4) : (tx * 4);
            float4 o;
            o.x = acc[i][jq*4+0] + bout[n0 + col0 + 0];
            o.y = acc[i][jq*4+1] + bout[n0 + col0 + 1];
            o.z = acc[i][jq*4+2] + bout[n0 + col0 + 2];
            o.w = acc[i][jq*4+3] + bout[n0 + col0 + 3];
            *(float4*)&out[base + col0] = o;
        }
    }
}

// ============ trap sentinel (should never fire now) =======================
__global__ void k_trap() { __trap(); }

// ============================== launcher ==================================
extern "C" void kernel_launch(void* const* d_in, const int* in_sizes, int n_in,
                              void* d_out, int out_size)
{
    // Measured ground-truth signature (R8 HXDBG dump): dict-insertion order.
    static const int SZ[21] = {65536, 2048, 1024000, 6144, 12288, 192, 192,
                               6144, 12288, 192, 192, 16384, 128, 16384, 128,
                               61440, 49152, 384, 384, 4096000, 32000};
    bool ok = (n_in == 21);
    if (ok) for (int i = 0; i < 21; i++) if (in_sizes[i] != SZ[i]) { ok = false; break; }
    if (!ok) { k_trap<<<1, 1>>>(); return; }

    const int*   inputs  = (const int*)  d_in[0];
    const int*   targets = (const int*)  d_in[1];
    const float* emb     = (const float*)d_in[2];
    const float* W_ih_f  = (const float*)d_in[3];
    const float* W_hh_f  = (const float*)d_in[4];
    const float* b_ih_f  = (const float*)d_in[5];
    const float* b_hh_f  = (const float*)d_in[6];
    const float* W_ih_b  = (const float*)d_in[7];
    const float* W_hh_b  = (const float*)d_in[8];
    const float* b_ih_b  = (const float*)d_in[9];
    const float* b_hh_b  = (const float*)d_in[10];
    const float* W1      = (const float*)d_in[11];
    const float* b1      = (const float*)d_in[12];
    const float* W2      = (const float*)d_in[13];
    const float* b2      = (const float*)d_in[14];
    const float* W_ih_d  = (const float*)d_in[15];
    const float* W_hh_d  = (const float*)d_in[16];
    const float* b_ih_d  = (const float*)d_in[17];
    const float* b_hh_d  = (const float*)d_in[18];
    const float* W_out   = (const float*)d_in[19];
    const float* b_out   = (const float*)d_in[20];
    float* out = (float*)d_out;

    k_gi  <<<dim3(3, 512), 256>>>(inputs, emb, W_ih_f, W_ih_b, b_ih_f, b_ih_b);
    k_enc <<<256, 192>>>(W_hh_f, W_hh_b, b_hh_f, b_hh_b);
    k_c2  <<<128, 128>>>(W2, b1, b2);
    k_gate<<<dim3(1, 512), 256>>>(W1);
    k_dec_all<<<128, 256>>>(emb, targets, W_ih_d, W_hh_d, b_ih_d, b_hh_d);
    k_logits_all<<<dim3(250, 15), 256>>>(W_out, b_out, out);
}

// round 13
// speedup vs baseline: 1.6583x; 1.3611x over previous
#include <cuda_runtime.h>
#include <math.h>

#define Bq 128
#define Sq 512
#define Tq 16
#define Eq 32
#define Hq 128
#define G3 192
#define GD 384
#define XD 160
#define Vq 32000
#define NSTEP 15

// ---------------- device scratch (static globals; no runtime alloc) -------
static __device__ float g_gi_f[(size_t)Sq * Bq * G3];   // [t][b][192]
static __device__ float g_gi_b[(size_t)Sq * Bq * G3];   // [t][b][192]
static __device__ float g_enc [(size_t)Bq * Sq * Hq];   // raw encoder outputs [b][s][h]
static __device__ float g_encg[(size_t)Bq * Sq * Hq];   // gated encoder outputs
static __device__ float g_hdec[Bq * Hq];                // decoder initial hidden (sn)
static __device__ float g_c2  [Bq * Hq];                // sn@W2^T + b1 + b2
static __device__ float g_hall[(size_t)NSTEP * Bq * Hq];// h after each decoder step

__device__ __forceinline__ float sigf(float x) { return 1.f / (1.f + __expf(-x)); }

// ==== 128x128 fp32 tile, 256 thr, 8x8 micro, BK=16 DOUBLE-BUFFERED ========
// Thread (tx,ty) owns rows {ty*4..+3, 64+ty*4..+3} x cols {tx*4..+3, 64+tx*4..+3}.
#define DB_PROLOG()                                                            \
    __shared__ float As[2][16][132];                                           \
    __shared__ float Bs[2][16][132];                                           \
    float acc[8][8];                                                           \
    _Pragma("unroll") for (int i = 0; i < 8; i++)                              \
        _Pragma("unroll") for (int j = 0; j < 8; j++) acc[i][j] = 0.f;         \
    const int tid = threadIdx.x;                                               \
    const int tx = tid & 15, ty = tid >> 4;

// load one 128x16 A panel + 128x16 B panel into buffer `buf` (k offset K0)
#define DB_LOAD(buf, AROW, BROW, K0)                                           \
    {                                                                          \
        const int k0 = (K0);                                                   \
        _Pragma("unroll") for (int v = 0; v < 2; v++) {                        \
            int fid = tid * 2 + v;                                             \
            int m = fid >> 2, kq = fid & 3;                                    \
            const float* ap = (AROW);                                          \
            float4 w4 = *(const float4*)(ap + k0 + kq * 4);                    \
            As[buf][kq*4+0][m] = w4.x; As[buf][kq*4+1][m] = w4.y;              \
            As[buf][kq*4+2][m] = w4.z; As[buf][kq*4+3][m] = w4.w;              \
        }                                                                      \
        _Pragma("unroll") for (int v = 0; v < 2; v++) {                        \
            int fid = tid * 2 + v;                                             \
            int n = fid >> 2, kq = fid & 3;                                    \
            const float* bp = (BROW);                                          \
            float4 w4 = *(const float4*)(bp + k0 + kq * 4);                    \
            Bs[buf][kq*4+0][n] = w4.x; Bs[buf][kq*4+1][n] = w4.y;              \
            Bs[buf][kq*4+2][n] = w4.z; Bs[buf][kq*4+3][n] = w4.w;              \
        }                                                                      \
    }

#define DB_COMPUTE(buf)                                                        \
    _Pragma("unroll") for (int k = 0; k < 16; k++) {                           \
        float4 a0 = *(const float4*)&As[buf][k][ty * 4];                       \
        float4 a1 = *(const float4*)&As[buf][k][64 + ty * 4];                  \
        float4 b0 = *(const float4*)&Bs[buf][k][tx * 4];                       \
        float4 b1 = *(const float4*)&Bs[buf][k][64 + tx * 4];                  \
        float av[8] = {a0.x,a0.y,a0.z,a0.w, a1.x,a1.y,a1.z,a1.w};              \
        float bv[8] = {b0.x,b0.y,b0.z,b0.w, b1.x,b1.y,b1.z,b1.w};              \
        _Pragma("unroll") for (int i = 0; i < 8; i++)                          \
            _Pragma("unroll") for (int j = 0; j < 8; j++)                      \
                acc[i][j] += av[i] * bv[j];                                    \
    }

#define QROW(q) (((q) < 4) ? (ty * 4 + (q)) : (60 + ty * 4 + (q)))
#define QCOL(q) (((q) < 4) ? (tx * 4 + (q)) : (60 + tx * 4 + (q)))

// ================= K1: embedding gather + input projection ================
// M = S*B = 65536 (row r = t*B+b), N = 384, K = 32 (2 stages); grid (3, 512)
__global__ __launch_bounds__(256, 2) void k_gi(
    const int* __restrict__ inputs, const float* __restrict__ emb,
    const float* __restrict__ Wf, const float* __restrict__ Wb,
    const float* __restrict__ bf, const float* __restrict__ bb)
{
    __shared__ int tok[128];
    const int m0 = blockIdx.y * 128;
    const int n0 = blockIdx.x * 128;
    if (threadIdx.x < 128) {
        int r = m0 + threadIdx.x;
        tok[threadIdx.x] = inputs[(r & (Bq - 1)) * Sq + (r >> 7)];
    }
    __syncthreads();
    DB_PROLOG();
    DB_LOAD(0,
            emb + (size_t)tok[m] * Eq,
            ((n0 + n) < G3) ? (Wf + (n0 + n) * Eq) : (Wb + (n0 + n - G3) * Eq),
            0);
    __syncthreads();
    DB_LOAD(1,
            emb + (size_t)tok[m] * Eq,
            ((n0 + n) < G3) ? (Wf + (n0 + n) * Eq) : (Wb + (n0 + n - G3) * Eq),
            16);
    DB_COMPUTE(0);
    __syncthreads();
    DB_COMPUTE(1);

    #pragma unroll
    for (int i = 0; i < 8; i++) {
        int r = m0 + QROW(i);
        #pragma unroll
        for (int j = 0; j < 8; j++) {
            int col = n0 + QCOL(j);
            float v = acc[i][j];
            if (col < G3) g_gi_f[(size_t)r * G3 + col] = v + bf[col];
            else          g_gi_b[(size_t)r * G3 + (col - G3)] = v + bb[col - G3];
        }
    }
}

// ==================== K2: encoder recurrence (both dirs) ==================
__global__ __launch_bounds__(192) void k_enc(
    const float* __restrict__ Whf, const float* __restrict__ Whb,
    const float* __restrict__ bhf, const float* __restrict__ bhb)
{
    const int b   = blockIdx.x & 127;
    const int dir = blockIdx.x >> 7;
    const int g   = threadIdx.x;
    const float* Wh = dir ? Whb : Whf;
    const float* bh = dir ? bhb : bhf;
    const float* gi = dir ? g_gi_b : g_gi_f;

    __shared__ float h_sh[64];
    __shared__ float gh_sh[G3];
    __shared__ float gi_sh[G3];

    float w[64];
    #pragma unroll
    for (int k = 0; k < 64; k++) w[k] = Wh[g * 64 + k];
    const float bhg = bh[g];
    if (g < 64) h_sh[g] = 0.f;
    __syncthreads();

    int t = dir ? (Sq - 1) : 0;
    const int dt = dir ? -1 : 1;
    float gcur = gi[((size_t)t * Bq + b) * G3 + g];

    for (int it = 0; it < Sq; it++, t += dt) {
        float gnext = 0.f;
        if (it + 1 < Sq) gnext = gi[((size_t)(t + dt) * Bq + b) * G3 + g];
        float a0 = bhg, a1 = 0.f, a2 = 0.f, a3 = 0.f;
        #pragma unroll
        for (int k = 0; k < 64; k += 4) {
            a0 += h_sh[k + 0] * w[k + 0];
            a1 += h_sh[k + 1] * w[k + 1];
            a2 += h_sh[k + 2] * w[k + 2];
            a3 += h_sh[k + 3] * w[k + 3];
        }
        gh_sh[g] = (a0 + a1) + (a2 + a3);
        gi_sh[g] = gcur;
        __syncthreads();
        if (g < 64) {
            float r  = sigf(gi_sh[g] + gh_sh[g]);
            float z  = sigf(gi_sh[64 + g] + gh_sh[64 + g]);
            float n  = tanhf(gi_sh[128 + g] + r * gh_sh[128 + g]);
            float hn = (1.f - z) * n + z * h_sh[g];
            h_sh[g] = hn;
            g_enc[((size_t)b * Sq + t) * Hq + dir * 64 + g] = hn;
        }
        __syncthreads();
        gcur = gnext;
    }
    if (g < 64) g_hdec[b * Hq + dir * 64 + g] = h_sh[g];
}

// ========= K3: c2[b][h] = sn@W2^T + b1 + b2 ================================
__global__ __launch_bounds__(128) void k_c2(
    const float* __restrict__ W2, const float* __restrict__ b1,
    const float* __restrict__ b2)
{
    const int b = blockIdx.x, h = threadIdx.x;
    __shared__ float sn[128];
    sn[h] = g_hdec[b * 128 + h];
    __syncthreads();
    float a = b1[h] + b2[h];
    const float* wr = W2 + h * 128;
    #pragma unroll 8
    for (int k = 0; k < 128; k++) a += sn[k] * wr[k];
    g_c2[b * 128 + h] = a;
}

// ===== K4: sGate GEMM + gating (K=128, 8 stages) ==========================
// M = B*S = 65536 (row r = b*S+s), N = 128; grid (1, 512)
__global__ __launch_bounds__(256, 2) void k_gate(const float* __restrict__ W1)
{
    const int m0 = blockIdx.y * 128;
    DB_PROLOG();
    DB_LOAD(0, g_enc + (size_t)(m0 + m) * Hq, W1 + n * 128, 0);
    __syncthreads();
    #pragma unroll
    for (int s = 0; s < 8; s++) {
        if (s < 7) DB_LOAD((s + 1) & 1,
                           g_enc + (size_t)(m0 + m) * Hq,
                           W1 + n * 128,
                           (s + 1) * 16);
        DB_COMPUTE(s & 1);
        __syncthreads();
    }
    #pragma unroll
    for (int i = 0; i < 8; i++) {
        int r = m0 + QROW(i);
        int bb2 = r >> 9;  // b = r / S
        #pragma unroll
        for (int j = 0; j < 8; j++) {
            int col = QCOL(j);
            float u   = acc[i][j] + g_c2[bb2 * 128 + col];
            float raw = g_enc[(size_t)r * Hq + col];
            g_encg[(size_t)r * Hq + col] = raw * sigf(u);
        }
    }
}

// ====== K5: persistent decoder (512 thr): 15 steps attention+GRU per b ====
__global__ __launch_bounds__(512) void k_dec_all(
    const float* __restrict__ emb, const int* __restrict__ targets,
    const float* __restrict__ Wihd, const float* __restrict__ Whhd,
    const float* __restrict__ bihd, const float* __restrict__ bhhd)
{
    const int b = blockIdx.x;
    const int tid = threadIdx.x;
    const int lane = tid & 31, wrp = tid >> 5;   // 16 warps
    __shared__ float hsh[128];
    __shared__ float sc[512];
    __shared__ float wred[16];
    __shared__ float red[16][132];
    __shared__ float xe[XD];
    __shared__ float gis[GD];
    __shared__ float ghs[GD];

    if (tid < 128) hsh[tid] = g_hdec[b * 128 + tid];
    __syncthreads();

    const float* eb = g_encg + (size_t)b * Sq * Hq;

    for (int step = 0; step < NSTEP; step++) {
        // ---- scores: one s-row per thread (512 rows / 512 threads) ----
        float a = 0.f;
        {
            const float4* r0 = (const float4*)(eb + (size_t)tid * 128);
            #pragma unroll
            for (int q = 0; q < 32; q++) {
                float4 v = r0[q];
                a += v.x * hsh[q*4] + v.y * hsh[q*4+1]
                   + v.z * hsh[q*4+2] + v.w * hsh[q*4+3];
            }
        }
        // ---- softmax max ----
        float m = a;
        #pragma unroll
        for (int o = 16; o > 0; o >>= 1) m = fmaxf(m, __shfl_xor_sync(0xffffffffu, m, o));
        if (lane == 0) wred[wrp] = m;
        __syncthreads();
        float mx = wred[0];
        #pragma unroll
        for (int i = 1; i < 16; i++) mx = fmaxf(mx, wred[i]);

        float e = __expf(a - mx);
        sc[tid] = e;
        float s = e;
        #pragma unroll
        for (int o = 16; o > 0; o >>= 1) s += __shfl_xor_sync(0xffffffffu, s, o);
        __syncthreads();                 // wred(max) consumed; sc visible
        if (lane == 0) wred[wrp] = s;
        __syncthreads();
        float tot = 0.f;
        #pragma unroll
        for (int i = 0; i < 16; i++) tot += wred[i];
        float inv = 1.f / tot;

        // ---- context: warp w sums s in [w*32, w*32+32); lane owns 4 d ----
        float4 cacc = make_float4(0.f, 0.f, 0.f, 0.f);
        {
            const int sbase = wrp * 32;
            #pragma unroll 4
            for (int s2 = sbase; s2 < sbase + 32; s2++) {
                float4 v = *(const float4*)(eb + (size_t)s2 * 128 + lane * 4);
                float w4 = sc[s2];
                cacc.x += w4 * v.x; cacc.y += w4 * v.y;
                cacc.z += w4 * v.z; cacc.w += w4 * v.w;
            }
        }
        *(float4*)&red[wrp][lane * 4] = cacc;
        __syncthreads();
        if (tid < 128) {
            float c = 0.f;
            #pragma unroll
            for (int w2 = 0; w2 < 16; w2++) c += red[w2][tid];
            xe[tid] = c * inv;
        } else if (tid < 128 + Eq) {
            int d = tid - 128;
            int wrd = targets[b * Tq + step];
            xe[128 + d] = emb[(size_t)wrd * Eq + d];
        }
        __syncthreads();

        // ---- GRU: 16 warps x 24 gate rows, lane-strided dots ----
        #pragma unroll 2
        for (int i = 0; i < 24; i++) {
            const int row = wrp * 24 + i;
            const float* wi = Wihd + (size_t)row * XD;
            const float* wh = Whhd + (size_t)row * 128;
            float ai = 0.f, cc = 0.f;
            #pragma unroll
            for (int q = 0; q < 5; q++) ai += wi[lane + q * 32] * xe[lane + q * 32];
            #pragma unroll
            for (int q = 0; q < 4; q++) cc += wh[lane + q * 32] * hsh[lane + q * 32];
            #pragma unroll
            for (int o = 16; o > 0; o >>= 1) {
                ai += __shfl_down_sync(0xffffffffu, ai, o);
                cc += __shfl_down_sync(0xffffffffu, cc, o);
            }
            if (lane == 0) { gis[row] = ai; ghs[row] = cc; }
        }
        __syncthreads();

        if (tid < 128) {
            float gi0 = gis[tid]       + bihd[tid];
            float gh0 = ghs[tid]       + bhhd[tid];
            float gi1 = gis[128 + tid] + bihd[128 + tid];
            float gh1 = ghs[128 + tid] + bhhd[128 + tid];
            float gi2 = gis[256 + tid] + bihd[256 + tid];
            float gh2 = ghs[256 + tid] + bhhd[256 + tid];
            float r = sigf(gi0 + gh0);
            float z = sigf(gi1 + gh1);
            float n = tanhf(gi2 + r * gh2);
            float hn = (1.f - z) * n + z * hsh[tid];
            hsh[tid] = hn;
            g_hall[((size_t)step * Bq + b) * Hq + tid] = hn;
        }
        __syncthreads();
    }
}

// ========== K6: batched logits GEMM: M = 1920, N = 32000, K = 128 =========
// row r = step*B+b; out[b][step][v]; grid (250, 15)
__global__ __launch_bounds__(256, 2) void k_logits_all(
    const float* __restrict__ Wout, const float* __restrict__ bout,
    float* __restrict__ out)
{
    const int m0 = blockIdx.y * 128;
    const int n0 = blockIdx.x * 128;
    DB_PROLOG();
    DB_LOAD(0, g_hall + (size_t)(m0 + m) * Hq, Wout + (size_t)(n0 + n) * Hq, 0);
    __syncthreads();
    #pragma unroll
    for (int s = 0; s < 8; s++) {
        if (s < 7) DB_LOAD((s + 1) & 1,
                           g_hall + (size_t)(m0 + m) * Hq,
                           Wout + (size_t)(n0 + n) * Hq,
                           (s + 1) * 16);
        DB_COMPUTE(s & 1);
        __syncthreads();
    }
    #pragma unroll
    for (int i = 0; i < 8; i++) {
        int r = m0 + QROW(i);
        int step = r >> 7, b2 = r & 127;
        size_t base = ((size_t)b2 * NSTEP + step) * Vq + n0;
        #pragma unroll
        for (int jq = 0; jq < 2; jq++) {
            int col0 = jq ? (64 + tx * 4) : (tx * 4);
            float4 o;
            o.x = acc[i][jq*4+0] + bout[n0 + col0 + 0];
            o.y = acc[i][jq*4+1] + bout[n0 + col0 + 1];
            o.z = acc[i][jq*4+2] + bout[n0 + col0 + 2];
            o.w = acc[i][jq*4+3] + bout[n0 + col0 + 3];
            *(float4*)&out[base + col0] = o;
        }
    }
}

// ============ trap sentinel (should never fire now) =======================
__global__ void k_trap() { __trap(); }

// ============================== launcher ==================================
extern "C" void kernel_launch(void* const* d_in, const int* in_sizes, int n_in,
                              void* d_out, int out_size)
{
    // Measured ground-truth signature (R8 HXDBG dump): dict-insertion order.
    static const int SZ[21] = {65536, 2048, 1024000, 6144, 12288, 192, 192,
                               6144, 12288, 192, 192, 16384, 128, 16384, 128,
                               61440, 49152, 384, 384, 4096000, 32000};
    bool ok = (n_in == 21);
    if (ok) for (int i = 0; i < 21; i++) if (in_sizes[i] != SZ[i]) { ok = false; break; }
    if (!ok) { k_trap<<<1, 1>>>(); return; }

    const int*   inputs  = (const int*)  d_in[0];
    const int*   targets = (const int*)  d_in[1];
    const float* emb     = (const float*)d_in[2];
    const float* W_ih_f  = (const float*)d_in[3];
    const float* W_hh_f  = (const float*)d_in[4];
    const float* b_ih_f  = (const float*)d_in[5];
    const float* b_hh_f  = (const float*)d_in[6];
    const float* W_ih_b  = (const float*)d_in[7];
    const float* W_hh_b  = (const float*)d_in[8];
    const float* b_ih_b  = (const float*)d_in[9];
    const float* b_hh_b  = (const float*)d_in[10];
    const float* W1      = (const float*)d_in[11];
    const float* b1      = (const float*)d_in[12];
    const float* W2      = (const float*)d_in[13];
    const float* b2      = (const float*)d_in[14];
    const float* W_ih_d  = (const float*)d_in[15];
    const float* W_hh_d  = (const float*)d_in[16];
    const float* b_ih_d  = (const float*)d_in[17];
    const float* b_hh_d  = (const float*)d_in[18];
    const float* W_out   = (const float*)d_in[19];
    const float* b_out   = (const float*)d_in[20];
    float* out = (float*)d_out;

    k_gi  <<<dim3(3, 512), 256>>>(inputs, emb, W_ih_f, W_ih_b, b_ih_f, b_ih_b);
    k_enc <<<256, 192>>>(W_hh_f, W_hh_b, b_hh_f, b_hh_b);
    k_c2  <<<128, 128>>>(W2, b1, b2);
    k_gate<<<dim3(1, 512), 256>>>(W1);
    k_dec_all<<<128, 512>>>(emb, targets, W_ih_d, W_hh_d, b_ih_d, b_hh_d);
    k_logits_all<<<dim3(250, 15), 256>>>(W_out, b_out, out);
}

// round 14
// speedup vs baseline: 1.6961x; 1.0228x over previous
#include <cuda_runtime.h>
#include <math.h>
#include <stdint.h>

#define Bq 128
#define Sq 512
#define Tq 16
#define Eq 32
#define Hq 128
#define G3 192
#define GD 384
#define XD 160
#define Vq 32000
#define NSTEP 15

// ---------------- device scratch (static globals; no runtime alloc) -------
static __device__ float g_gi_f[(size_t)Sq * Bq * G3];   // [t][b][192]
static __device__ float g_gi_b[(size_t)Sq * Bq * G3];   // [t][b][192]
static __device__ float g_enc [(size_t)Bq * Sq * Hq];   // raw encoder outputs [b][s][h]
static __device__ float g_encg[(size_t)Bq * Sq * Hq];   // gated encoder outputs
static __device__ float g_hdec[Bq * Hq];                // decoder initial hidden (sn)
static __device__ float g_c2  [Bq * Hq];                // sn@W2^T + b1 + b2
static __device__ float g_hall[(size_t)NSTEP * Bq * Hq];// h after each decoder step

__device__ __forceinline__ float sigf(float x) { return 1.f / (1.f + __expf(-x)); }

__device__ __forceinline__ uint32_t f2tf(float x) {
    uint32_t u;
    asm("cvt.rna.tf32.f32 %0, %1;" : "=r"(u) : "f"(x));
    return u;
}

#define MMA_TF32(d, a0, a1, a2, a3, b0, b1)                                    \
    asm volatile(                                                              \
        "mma.sync.aligned.m16n8k8.row.col.f32.tf32.tf32.f32 "                  \
        "{%0,%1,%2,%3}, {%4,%5,%6,%7}, {%8,%9}, {%0,%1,%2,%3};"                \
        : "+f"((d)[0]), "+f"((d)[1]), "+f"((d)[2]), "+f"((d)[3])               \
        : "r"(a0), "r"(a1), "r"(a2), "r"(a3), "r"(b0), "r"(b1))

// ============ 128(M) x 128(N) fp32 tile, 256 thr, 8x8 micro (quadrants) ===
// (single-buffer BK=32 — measured faster than BK=16 double-buffer in R12/13)
#define G128_PROLOG()                                                          \
    __shared__ float As[32][132];                                              \
    __shared__ float Bs[32][132];                                              \
    float acc[8][8];                                                           \
    _Pragma("unroll") for (int i = 0; i < 8; i++)                              \
        _Pragma("unroll") for (int j = 0; j < 8; j++) acc[i][j] = 0.f;         \
    const int tid = threadIdx.x;                                               \
    const int tx = tid & 15, ty = tid >> 4;

#define G128_KSTEP(AROW, BROW, K0)                                             \
    {                                                                          \
        const int k0 = (K0);                                                   \
        _Pragma("unroll") for (int jj = 0; jj < 4; jj++) {                     \
            int fid = tid + jj * 256;                                          \
            int m = fid >> 3, kq = fid & 7;                                    \
            const float* ap = (AROW);                                          \
            float4 v = *(const float4*)(ap + k0 + kq * 4);                     \
            As[kq*4+0][m] = v.x; As[kq*4+1][m] = v.y;                          \
            As[kq*4+2][m] = v.z; As[kq*4+3][m] = v.w;                          \
        }                                                                      \
        _Pragma("unroll") for (int jj = 0; jj < 4; jj++) {                     \
            int fid = tid + jj * 256;                                          \
            int n = fid >> 3, kq = fid & 7;                                    \
            const float* bp = (BROW);                                          \
            float4 v = *(const float4*)(bp + k0 + kq * 4);                     \
            Bs[kq*4+0][n] = v.x; Bs[kq*4+1][n] = v.y;                          \
            Bs[kq*4+2][n] = v.z; Bs[kq*4+3][n] = v.w;                          \
        }                                                                      \
        __syncthreads();                                                       \
        _Pragma("unroll") for (int k = 0; k < 32; k++) {                       \
            float4 a0 = *(const float4*)&As[k][ty * 4];                        \
            float4 a1 = *(const float4*)&As[k][64 + ty * 4];                   \
            float4 b0 = *(const float4*)&Bs[k][tx * 4];                        \
            float4 b1 = *(const float4*)&Bs[k][64 + tx * 4];                   \
            float av[8] = {a0.x,a0.y,a0.z,a0.w, a1.x,a1.y,a1.z,a1.w};          \
            float bv[8] = {b0.x,b0.y,b0.z,b0.w, b1.x,b1.y,b1.z,b1.w};          \
            _Pragma("unroll") for (int i = 0; i < 8; i++)                      \
                _Pragma("unroll") for (int j = 0; j < 8; j++)                  \
                    acc[i][j] += av[i] * bv[j];                                \
        }                                                                      \
        __syncthreads();                                                       \
    }

#define QROW(q) (((q) < 4) ? (ty * 4 + (q)) : (60 + ty * 4 + (q)))
#define QCOL(q) (((q) < 4) ? (tx * 4 + (q)) : (60 + tx * 4 + (q)))

// ================= K1: embedding gather + input projection ================
// M = S*B = 65536 (row r = t*B+b), N = 384, K = 32; grid (3, 512)
__global__ __launch_bounds__(256, 2) void k_gi(
    const int* __restrict__ inputs, const float* __restrict__ emb,
    const float* __restrict__ Wf, const float* __restrict__ Wb,
    const float* __restrict__ bf, const float* __restrict__ bb)
{
    __shared__ int tok[128];
    const int m0 = blockIdx.y * 128;
    const int n0 = blockIdx.x * 128;
    if (threadIdx.x < 128) {
        int r = m0 + threadIdx.x;
        tok[threadIdx.x] = inputs[(r & (Bq - 1)) * Sq + (r >> 7)];
    }
    __syncthreads();
    G128_PROLOG();
    G128_KSTEP(emb + (size_t)tok[m] * Eq,
               ((n0 + n) < G3) ? (Wf + (n0 + n) * Eq)
                               : (Wb + (n0 + n - G3) * Eq),
               0);
    #pragma unroll
    for (int i = 0; i < 8; i++) {
        int r = m0 + QROW(i);
        #pragma unroll
        for (int j = 0; j < 8; j++) {
            int col = n0 + QCOL(j);
            float v = acc[i][j];
            if (col < G3) g_gi_f[(size_t)r * G3 + col] = v + bf[col];
            else          g_gi_b[(size_t)r * G3 + (col - G3)] = v + bb[col - G3];
        }
    }
}

// ==================== K2: encoder recurrence (both dirs) ==================
__global__ __launch_bounds__(192) void k_enc(
    const float* __restrict__ Whf, const float* __restrict__ Whb,
    const float* __restrict__ bhf, const float* __restrict__ bhb)
{
    const int b   = blockIdx.x & 127;
    const int dir = blockIdx.x >> 7;
    const int g   = threadIdx.x;
    const float* Wh = dir ? Whb : Whf;
    const float* bh = dir ? bhb : bhf;
    const float* gi = dir ? g_gi_b : g_gi_f;

    __shared__ float h_sh[64];
    __shared__ float gh_sh[G3];
    __shared__ float gi_sh[G3];

    float w[64];
    #pragma unroll
    for (int k = 0; k < 64; k++) w[k] = Wh[g * 64 + k];
    const float bhg = bh[g];
    if (g < 64) h_sh[g] = 0.f;
    __syncthreads();

    int t = dir ? (Sq - 1) : 0;
    const int dt = dir ? -1 : 1;
    float gcur = gi[((size_t)t * Bq + b) * G3 + g];

    for (int it = 0; it < Sq; it++, t += dt) {
        float gnext = 0.f;
        if (it + 1 < Sq) gnext = gi[((size_t)(t + dt) * Bq + b) * G3 + g];
        float a0 = bhg, a1 = 0.f, a2 = 0.f, a3 = 0.f;
        #pragma unroll
        for (int k = 0; k < 64; k += 4) {
            a0 += h_sh[k + 0] * w[k + 0];
            a1 += h_sh[k + 1] * w[k + 1];
            a2 += h_sh[k + 2] * w[k + 2];
            a3 += h_sh[k + 3] * w[k + 3];
        }
        gh_sh[g] = (a0 + a1) + (a2 + a3);
        gi_sh[g] = gcur;
        __syncthreads();
        if (g < 64) {
            float r  = sigf(gi_sh[g] + gh_sh[g]);
            float z  = sigf(gi_sh[64 + g] + gh_sh[64 + g]);
            float n  = tanhf(gi_sh[128 + g] + r * gh_sh[128 + g]);
            float hn = (1.f - z) * n + z * h_sh[g];
            h_sh[g] = hn;
            g_enc[((size_t)b * Sq + t) * Hq + dir * 64 + g] = hn;
        }
        __syncthreads();
        gcur = gnext;
    }
    if (g < 64) g_hdec[b * Hq + dir * 64 + g] = h_sh[g];
}

// ========= K3: c2[b][h] = sn@W2^T + b1 + b2 ================================
__global__ __launch_bounds__(128) void k_c2(
    const float* __restrict__ W2, const float* __restrict__ b1,
    const float* __restrict__ b2)
{
    const int b = blockIdx.x, h = threadIdx.x;
    __shared__ float sn[128];
    sn[h] = g_hdec[b * 128 + h];
    __syncthreads();
    float a = b1[h] + b2[h];
    const float* wr = W2 + h * 128;
    #pragma unroll 8
    for (int k = 0; k < 128; k++) a += sn[k] * wr[k];
    g_c2[b * 128 + h] = a;
}

// ===== K4: sGate GEMM + gating =============================================
// M = B*S = 65536 (row r = b*S+s), N = 128, K = 128; grid (1, 512)
__global__ __launch_bounds__(256, 2) void k_gate(const float* __restrict__ W1)
{
    const int m0 = blockIdx.y * 128;
    G128_PROLOG();
    for (int kk = 0; kk < 128; kk += 32) {
        G128_KSTEP(g_enc + (size_t)(m0 + m) * Hq,
                   W1 + n * 128,
                   kk);
    }
    #pragma unroll
    for (int i = 0; i < 8; i++) {
        int r = m0 + QROW(i);
        int bb2 = r >> 9;  // b = r / S
        #pragma unroll
        for (int j = 0; j < 8; j++) {
            int col = QCOL(j);
            float u   = acc[i][j] + g_c2[bb2 * 128 + col];
            float raw = g_enc[(size_t)r * Hq + col];
            g_encg[(size_t)r * Hq + col] = raw * sigf(u);
        }
    }
}

// ====== K5: persistent decoder (512 thr): 15 steps attention+GRU per b ====
__global__ __launch_bounds__(512) void k_dec_all(
    const float* __restrict__ emb, const int* __restrict__ targets,
    const float* __restrict__ Wihd, const float* __restrict__ Whhd,
    const float* __restrict__ bihd, const float* __restrict__ bhhd)
{
    const int b = blockIdx.x;
    const int tid = threadIdx.x;
    const int lane = tid & 31, wrp = tid >> 5;   // 16 warps
    __shared__ float hsh[128];
    __shared__ float sc[512];
    __shared__ float wred[16];
    __shared__ float red[16][132];
    __shared__ float xe[XD];
    __shared__ float gis[GD];
    __shared__ float ghs[GD];

    if (tid < 128) hsh[tid] = g_hdec[b * 128 + tid];
    __syncthreads();

    const float* eb = g_encg + (size_t)b * Sq * Hq;

    for (int step = 0; step < NSTEP; step++) {
        // ---- scores: one s-row per thread ----
        float a = 0.f;
        {
            const float4* r0 = (const float4*)(eb + (size_t)tid * 128);
            #pragma unroll
            for (int q = 0; q < 32; q++) {
                float4 v = r0[q];
                a += v.x * hsh[q*4] + v.y * hsh[q*4+1]
                   + v.z * hsh[q*4+2] + v.w * hsh[q*4+3];
            }
        }
        float m = a;
        #pragma unroll
        for (int o = 16; o > 0; o >>= 1) m = fmaxf(m, __shfl_xor_sync(0xffffffffu, m, o));
        if (lane == 0) wred[wrp] = m;
        __syncthreads();
        float mx = wred[0];
        #pragma unroll
        for (int i = 1; i < 16; i++) mx = fmaxf(mx, wred[i]);

        float e = __expf(a - mx);
        sc[tid] = e;
        float s = e;
        #pragma unroll
        for (int o = 16; o > 0; o >>= 1) s += __shfl_xor_sync(0xffffffffu, s, o);
        __syncthreads();
        if (lane == 0) wred[wrp] = s;
        __syncthreads();
        float tot = 0.f;
        #pragma unroll
        for (int i = 0; i < 16; i++) tot += wred[i];
        float inv = 1.f / tot;

        // ---- context: warp w sums s in [w*32, w*32+32); lane owns 4 d ----
        float4 cacc = make_float4(0.f, 0.f, 0.f, 0.f);
        {
            const int sbase = wrp * 32;
            #pragma unroll 4
            for (int s2 = sbase; s2 < sbase + 32; s2++) {
                float4 v = *(const float4*)(eb + (size_t)s2 * 128 + lane * 4);
                float w4 = sc[s2];
                cacc.x += w4 * v.x; cacc.y += w4 * v.y;
                cacc.z += w4 * v.z; cacc.w += w4 * v.w;
            }
        }
        *(float4*)&red[wrp][lane * 4] = cacc;
        __syncthreads();
        if (tid < 128) {
            float c = 0.f;
            #pragma unroll
            for (int w2 = 0; w2 < 16; w2++) c += red[w2][tid];
            xe[tid] = c * inv;
        } else if (tid < 128 + Eq) {
            int d = tid - 128;
            int wrd = targets[b * Tq + step];
            xe[128 + d] = emb[(size_t)wrd * Eq + d];
        }
        __syncthreads();

        // ---- GRU: 16 warps x 24 gate rows ----
        #pragma unroll 2
        for (int i = 0; i < 24; i++) {
            const int row = wrp * 24 + i;
            const float* wi = Wihd + (size_t)row * XD;
            const float* wh = Whhd + (size_t)row * 128;
            float ai = 0.f, cc = 0.f;
            #pragma unroll
            for (int q = 0; q < 5; q++) ai += wi[lane + q * 32] * xe[lane + q * 32];
            #pragma unroll
            for (int q = 0; q < 4; q++) cc += wh[lane + q * 32] * hsh[lane + q * 32];
            #pragma unroll
            for (int o = 16; o > 0; o >>= 1) {
                ai += __shfl_down_sync(0xffffffffu, ai, o);
                cc += __shfl_down_sync(0xffffffffu, cc, o);
            }
            if (lane == 0) { gis[row] = ai; ghs[row] = cc; }
        }
        __syncthreads();

        if (tid < 128) {
            float gi0 = gis[tid]       + bihd[tid];
            float gh0 = ghs[tid]       + bhhd[tid];
            float gi1 = gis[128 + tid] + bihd[128 + tid];
            float gh1 = ghs[128 + tid] + bhhd[128 + tid];
            float gi2 = gis[256 + tid] + bihd[256 + tid];
            float gh2 = ghs[256 + tid] + bhhd[256 + tid];
            float r = sigf(gi0 + gh0);
            float z = sigf(gi1 + gh1);
            float n = tanhf(gi2 + r * gh2);
            float hn = (1.f - z) * n + z * hsh[tid];
            hsh[tid] = hn;
            g_hall[((size_t)step * Bq + b) * Hq + tid] = hn;
        }
        __syncthreads();
    }
}

// ====== K6: logits via split-tf32 MMA: M = 1920, N = 32000, K = 128 =======
// C = H @ Wout^T. grid (250 ntiles, 15 mtiles), 256 thr = 8 warps (2m x 4n).
// Split-tf32: x = hi + lo (each tf32); A*B ~= Ah*Bh + Ah*Bl + Al*Bh (err ~1e-7).
__global__ __launch_bounds__(256) void k_logits_mma(
    const float* __restrict__ Wout, const float* __restrict__ bout,
    float* __restrict__ out)
{
    const int tid = threadIdx.x;
    const int lane = tid & 31, wrp = tid >> 5;
    const int wm = wrp & 1, wn = wrp >> 1;      // 2 x 4 warp grid
    const int gr = lane >> 2, tg = lane & 3;
    const int m0 = blockIdx.y * 128;            // step = blockIdx.y
    const int n0 = blockIdx.x * 128;

    __shared__ float Hs[128][33];
    __shared__ float Ws[128][33];

    float acc[4][4][4];
    #pragma unroll
    for (int i = 0; i < 4; i++)
        #pragma unroll
        for (int j = 0; j < 4; j++)
            #pragma unroll
            for (int q = 0; q < 4; q++) acc[i][j][q] = 0.f;

    for (int kc = 0; kc < 4; kc++) {            // K chunks of 32
        const int kb = kc * 32;
        // load H panel (128 x 32) and W panel (128 x 32), coalesced float4
        #pragma unroll
        for (int j = 0; j < 4; j++) {
            int f = tid + j * 256;
            int row = f >> 3, c4 = f & 7;
            float4 v = *(const float4*)&g_hall[(size_t)(m0 + row) * Hq + kb + c4 * 4];
            Hs[row][c4*4+0] = v.x; Hs[row][c4*4+1] = v.y;
            Hs[row][c4*4+2] = v.z; Hs[row][c4*4+3] = v.w;
            float4 w = *(const float4*)&Wout[(size_t)(n0 + row) * Hq + kb + c4 * 4];
            Ws[row][c4*4+0] = w.x; Ws[row][c4*4+1] = w.y;
            Ws[row][c4*4+2] = w.z; Ws[row][c4*4+3] = w.w;
        }
        __syncthreads();

        #pragma unroll
        for (int k8 = 0; k8 < 4; k8++) {
            const int k0 = k8 * 8;
            // B fragments for all 4 n-tiles
            uint32_t bh[4][2], bl[4][2];
            #pragma unroll
            for (int nt = 0; nt < 4; nt++) {
                int nn = wn * 32 + nt * 8 + gr;
                float y0 = Ws[nn][k0 + tg];
                float y1 = Ws[nn][k0 + tg + 4];
                bh[nt][0] = f2tf(y0); bl[nt][0] = f2tf(y0 - __uint_as_float(bh[nt][0]));
                bh[nt][1] = f2tf(y1); bl[nt][1] = f2tf(y1 - __uint_as_float(bh[nt][1]));
            }
            #pragma unroll
            for (int mt = 0; mt < 4; mt++) {
                int r0 = wm * 64 + mt * 16 + gr;
                float x0 = Hs[r0][k0 + tg];
                float x1 = Hs[r0 + 8][k0 + tg];
                float x2 = Hs[r0][k0 + tg + 4];
                float x3 = Hs[r0 + 8][k0 + tg + 4];
                uint32_t ah0 = f2tf(x0), al0 = f2tf(x0 - __uint_as_float(ah0));
                uint32_t ah1 = f2tf(x1), al1 = f2tf(x1 - __uint_as_float(ah1));
                uint32_t ah2 = f2tf(x2), al2 = f2tf(x2 - __uint_as_float(ah2));
                uint32_t ah3 = f2tf(x3), al3 = f2tf(x3 - __uint_as_float(ah3));
                #pragma unroll
                for (int nt = 0; nt < 4; nt++) {
                    MMA_TF32(acc[mt][nt], ah0, ah1, ah2, ah3, bh[nt][0], bh[nt][1]);
                    MMA_TF32(acc[mt][nt], ah0, ah1, ah2, ah3, bl[nt][0], bl[nt][1]);
                    MMA_TF32(acc[mt][nt], al0, al1, al2, al3, bh[nt][0], bh[nt][1]);
                }
            }
        }
        __syncthreads();
    }

    // epilogue: c0,c1 at (row, col..col+1), c2,c3 at (row+8, ...)
    const int step = blockIdx.y;
    #pragma unroll
    for (int mt = 0; mt < 4; mt++) {
        int b2 = wm * 64 + mt * 16 + gr;
        #pragma unroll
        for (int nt = 0; nt < 4; nt++) {
            int col = n0 + wn * 32 + nt * 8 + 2 * tg;
            float bo0 = bout[col], bo1 = bout[col + 1];
            size_t base0 = ((size_t)b2 * NSTEP + step) * Vq;
            out[base0 + col]     = acc[mt][nt][0] + bo0;
            out[base0 + col + 1] = acc[mt][nt][1] + bo1;
            size_t base1 = ((size_t)(b2 + 8) * NSTEP + step) * Vq;
            out[base1 + col]     = acc[mt][nt][2] + bo0;
            out[base1 + col + 1] = acc[mt][nt][3] + bo1;
        }
    }
}

// ============ trap sentinel (should never fire now) =======================
__global__ void k_trap() { __trap(); }

// ============================== launcher ==================================
extern "C" void kernel_launch(void* const* d_in, const int* in_sizes, int n_in,
                              void* d_out, int out_size)
{
    // Measured ground-truth signature (R8 HXDBG dump): dict-insertion order.
    static const int SZ[21] = {65536, 2048, 1024000, 6144, 12288, 192, 192,
                               6144, 12288, 192, 192, 16384, 128, 16384, 128,
                               61440, 49152, 384, 384, 4096000, 32000};
    bool ok = (n_in == 21);
    if (ok) for (int i = 0; i < 21; i++) if (in_sizes[i] != SZ[i]) { ok = false; break; }
    if (!ok) { k_trap<<<1, 1>>>(); return; }

    const int*   inputs  = (const int*)  d_in[0];
    const int*   targets = (const int*)  d_in[1];
    const float* emb     = (const float*)d_in[2];
    const float* W_ih_f  = (const float*)d_in[3];
    const float* W_hh_f  = (const float*)d_in[4];
    const float* b_ih_f  = (const float*)d_in[5];
    const float* b_hh_f  = (const float*)d_in[6];
    const float* W_ih_b  = (const float*)d_in[7];
    const float* W_hh_b  = (const float*)d_in[8];
    const float* b_ih_b  = (const float*)d_in[9];
    const float* b_hh_b  = (const float*)d_in[10];
    const float* W1      = (const float*)d_in[11];
    const float* b1      = (const float*)d_in[12];
    const float* W2      = (const float*)d_in[13];
    const float* b2      = (const float*)d_in[14];
    const float* W_ih_d  = (const float*)d_in[15];
    const float* W_hh_d  = (const float*)d_in[16];
    const float* b_ih_d  = (const float*)d_in[17];
    const float* b_hh_d  = (const float*)d_in[18];
    const float* W_out   = (const float*)d_in[19];
    const float* b_out   = (const float*)d_in[20];
    float* out = (float*)d_out;

    k_gi  <<<dim3(3, 512), 256>>>(inputs, emb, W_ih_f, W_ih_b, b_ih_f, b_ih_b);
    k_enc <<<256, 192>>>(W_hh_f, W_hh_b, b_hh_f, b_hh_b);
    k_c2  <<<128, 128>>>(W2, b1, b2);
    k_gate<<<dim3(1, 512), 256>>>(W1);
    k_dec_all<<<128, 512>>>(emb, targets, W_ih_d, W_hh_d, b_ih_d, b_hh_d);
    k_logits_mma<<<dim3(250, 15), 256>>>(W_out, b_out, out);
}

// round 16
// speedup vs baseline: 2.0217x; 1.1919x over previous
#include <cuda_runtime.h>
#include <cuda_bf16.h>
#include <math.h>
#include <stdint.h>

#define Bq 128
#define Sq 512
#define Tq 16
#define Eq 32
#define Hq 128
#define G3 192
#define GD 384
#define XD 160
#define Vq 32000
#define NSTEP 15

// ---------------- device scratch (static globals; no runtime alloc) -------
static __device__ float g_gi_f[(size_t)Sq * Bq * G3];
static __device__ float g_gi_b[(size_t)Sq * Bq * G3];
static __device__ float g_enc [(size_t)Bq * Sq * Hq];
static __device__ float g_encg[(size_t)Bq * Sq * Hq];
static __device__ float g_hdec[Bq * Hq];
static __device__ float g_c2  [Bq * Hq];
static __device__ __nv_bfloat16 g_W1b[(size_t)Vq * Hq];      // Wout hi
static __device__ __nv_bfloat16 g_W2b[(size_t)Vq * Hq];      // Wout lo
static __device__ __nv_bfloat16 g_H1b[(size_t)NSTEP * Bq * Hq];
static __device__ __nv_bfloat16 g_H2b[(size_t)NSTEP * Bq * Hq];

__device__ __forceinline__ float sigf(float x) { return 1.f / (1.f + __expf(-x)); }

#define MMA_BF16(d, a0, a1, a2, a3, b0, b1)                                    \
    asm volatile(                                                              \
        "mma.sync.aligned.m16n8k16.row.col.f32.bf16.bf16.f32 "                 \
        "{%0,%1,%2,%3}, {%4,%5,%6,%7}, {%8,%9}, {%0,%1,%2,%3};"                \
        : "+f"((d)[0]), "+f"((d)[1]), "+f"((d)[2]), "+f"((d)[3])               \
        : "r"(a0), "r"(a1), "r"(a2), "r"(a3), "r"(b0), "r"(b1))

// ============ 128x128 fp32 tile, 256 thr, 8x8 micro (single-buffer) =======
#define G128_PROLOG()                                                          \
    __shared__ float As[32][132];                                              \
    __shared__ float Bs[32][132];                                              \
    float acc[8][8];                                                           \
    _Pragma("unroll") for (int i = 0; i < 8; i++)                              \
        _Pragma("unroll") for (int j = 0; j < 8; j++) acc[i][j] = 0.f;         \
    const int tid = threadIdx.x;                                               \
    const int tx = tid & 15, ty = tid >> 4;

#define G128_KSTEP(AROW, BROW, K0)                                             \
    {                                                                          \
        const int k0 = (K0);                                                   \
        _Pragma("unroll") for (int jj = 0; jj < 4; jj++) {                     \
            int fid = tid + jj * 256;                                          \
            int m = fid >> 3, kq = fid & 7;                                    \
            const float* ap = (AROW);                                          \
            float4 v = *(const float4*)(ap + k0 + kq * 4);                     \
            As[kq*4+0][m] = v.x; As[kq*4+1][m] = v.y;                          \
            As[kq*4+2][m] = v.z; As[kq*4+3][m] = v.w;                          \
        }                                                                      \
        _Pragma("unroll") for (int jj = 0; jj < 4; jj++) {                     \
            int fid = tid + jj * 256;                                          \
            int n = fid >> 3, kq = fid & 7;                                    \
            const float* bp = (BROW);                                          \
            float4 v = *(const float4*)(bp + k0 + kq * 4);                     \
            Bs[kq*4+0][n] = v.x; Bs[kq*4+1][n] = v.y;                          \
            Bs[kq*4+2][n] = v.z; Bs[kq*4+3][n] = v.w;                          \
        }                                                                      \
        __syncthreads();                                                       \
        _Pragma("unroll") for (int k = 0; k < 32; k++) {                       \
            float4 a0 = *(const float4*)&As[k][ty * 4];                        \
            float4 a1 = *(const float4*)&As[k][64 + ty * 4];                   \
            float4 b0 = *(const float4*)&Bs[k][tx * 4];                        \
            float4 b1 = *(const float4*)&Bs[k][64 + tx * 4];                   \
            float av[8] = {a0.x,a0.y,a0.z,a0.w, a1.x,a1.y,a1.z,a1.w};          \
            float bv[8] = {b0.x,b0.y,b0.z,b0.w, b1.x,b1.y,b1.z,b1.w};          \
            _Pragma("unroll") for (int i = 0; i < 8; i++)                      \
                _Pragma("unroll") for (int j = 0; j < 8; j++)                  \
                    acc[i][j] += av[i] * bv[j];                                \
        }                                                                      \
        __syncthreads();                                                       \
    }

#define QROW(q) (((q) < 4) ? (ty * 4 + (q)) : (60 + ty * 4 + (q)))
#define QCOL(q) (((q) < 4) ? (tx * 4 + (q)) : (60 + tx * 4 + (q)))

// ================= K1: embedding gather + input projection ================
__global__ __launch_bounds__(256, 2) void k_gi(
    const int* __restrict__ inputs, const float* __restrict__ emb,
    const float* __restrict__ Wf, const float* __restrict__ Wb,
    const float* __restrict__ bf, const float* __restrict__ bb)
{
    __shared__ int tok[128];
    const int m0 = blockIdx.y * 128;
    const int n0 = blockIdx.x * 128;
    if (threadIdx.x < 128) {
        int r = m0 + threadIdx.x;
        tok[threadIdx.x] = inputs[(r & (Bq - 1)) * Sq + (r >> 7)];
    }
    __syncthreads();
    G128_PROLOG();
    G128_KSTEP(emb + (size_t)tok[m] * Eq,
               ((n0 + n) < G3) ? (Wf + (n0 + n) * Eq)
                               : (Wb + (n0 + n - G3) * Eq),
               0);
    #pragma unroll
    for (int i = 0; i < 8; i++) {
        int r = m0 + QROW(i);
        #pragma unroll
        for (int j = 0; j < 8; j++) {
            int col = n0 + QCOL(j);
            float v = acc[i][j];
            if (col < G3) g_gi_f[(size_t)r * G3 + col] = v + bf[col];
            else          g_gi_b[(size_t)r * G3 + (col - G3)] = v + bb[col - G3];
        }
    }
}

// ==================== K2: encoder recurrence (both dirs) ==================
__global__ __launch_bounds__(192) void k_enc(
    const float* __restrict__ Whf, const float* __restrict__ Whb,
    const float* __restrict__ bhf, const float* __restrict__ bhb)
{
    const int b   = blockIdx.x & 127;
    const int dir = blockIdx.x >> 7;
    const int g   = threadIdx.x;
    const float* Wh = dir ? Whb : Whf;
    const float* bh = dir ? bhb : bhf;
    const float* gi = dir ? g_gi_b : g_gi_f;

    __shared__ float h_sh[64];
    __shared__ float gh_sh[G3];
    __shared__ float gi_sh[G3];

    float w[64];
    #pragma unroll
    for (int k = 0; k < 64; k++) w[k] = Wh[g * 64 + k];
    const float bhg = bh[g];
    if (g < 64) h_sh[g] = 0.f;
    __syncthreads();

    int t = dir ? (Sq - 1) : 0;
    const int dt = dir ? -1 : 1;
    float gcur = gi[((size_t)t * Bq + b) * G3 + g];

    for (int it = 0; it < Sq; it++, t += dt) {
        float gnext = 0.f;
        if (it + 1 < Sq) gnext = gi[((size_t)(t + dt) * Bq + b) * G3 + g];
        float a0 = bhg, a1 = 0.f, a2 = 0.f, a3 = 0.f;
        #pragma unroll
        for (int k = 0; k < 64; k += 4) {
            a0 += h_sh[k + 0] * w[k + 0];
            a1 += h_sh[k + 1] * w[k + 1];
            a2 += h_sh[k + 2] * w[k + 2];
            a3 += h_sh[k + 3] * w[k + 3];
        }
        gh_sh[g] = (a0 + a1) + (a2 + a3);
        gi_sh[g] = gcur;
        __syncthreads();
        if (g < 64) {
            float r  = sigf(gi_sh[g] + gh_sh[g]);
            float z  = sigf(gi_sh[64 + g] + gh_sh[64 + g]);
            float n  = tanhf(gi_sh[128 + g] + r * gh_sh[128 + g]);
            float hn = (1.f - z) * n + z * h_sh[g];
            h_sh[g] = hn;
            g_enc[((size_t)b * Sq + t) * Hq + dir * 64 + g] = hn;
        }
        __syncthreads();
        gcur = gnext;
    }
    if (g < 64) g_hdec[b * Hq + dir * 64 + g] = h_sh[g];
}

// ========= K3: c2[b][h] = sn@W2^T + b1 + b2 ================================
__global__ __launch_bounds__(128) void k_c2(
    const float* __restrict__ W2, const float* __restrict__ b1,
    const float* __restrict__ b2)
{
    const int b = blockIdx.x, h = threadIdx.x;
    __shared__ float sn[128];
    sn[h] = g_hdec[b * 128 + h];
    __syncthreads();
    float a = b1[h] + b2[h];
    const float* wr = W2 + h * 128;
    #pragma unroll 8
    for (int k = 0; k < 128; k++) a += sn[k] * wr[k];
    g_c2[b * 128 + h] = a;
}

// ===== K4: sGate GEMM + gating =============================================
__global__ __launch_bounds__(256, 2) void k_gate(const float* __restrict__ W1)
{
    const int m0 = blockIdx.y * 128;
    G128_PROLOG();
    for (int kk = 0; kk < 128; kk += 32) {
        G128_KSTEP(g_enc + (size_t)(m0 + m) * Hq,
                   W1 + n * 128,
                   kk);
    }
    #pragma unroll
    for (int i = 0; i < 8; i++) {
        int r = m0 + QROW(i);
        int bb2 = r >> 9;
        #pragma unroll
        for (int j = 0; j < 8; j++) {
            int col = QCOL(j);
            float u   = acc[i][j] + g_c2[bb2 * 128 + col];
            float raw = g_enc[(size_t)r * Hq + col];
            g_encg[(size_t)r * Hq + col] = raw * sigf(u);
        }
    }
}

// ====== K5: persistent decoder (512 thr) + bf16-split H epilogue ==========
__global__ __launch_bounds__(512) void k_dec_all(
    const float* __restrict__ emb, const int* __restrict__ targets,
    const float* __restrict__ Wihd, const float* __restrict__ Whhd,
    const float* __restrict__ bihd, const float* __restrict__ bhhd)
{
    const int b = blockIdx.x;
    const int tid = threadIdx.x;
    const int lane = tid & 31, wrp = tid >> 5;
    __shared__ float hsh[128];
    __shared__ float sc[512];
    __shared__ float wred[16];
    __shared__ float red[16][132];
    __shared__ float xe[XD];
    __shared__ float gis[GD];
    __shared__ float ghs[GD];

    if (tid < 128) hsh[tid] = g_hdec[b * 128 + tid];
    __syncthreads();

    const float* eb = g_encg + (size_t)b * Sq * Hq;

    for (int step = 0; step < NSTEP; step++) {
        float a = 0.f;
        {
            const float4* r0 = (const float4*)(eb + (size_t)tid * 128);
            #pragma unroll
            for (int q = 0; q < 32; q++) {
                float4 v = r0[q];
                a += v.x * hsh[q*4] + v.y * hsh[q*4+1]
                   + v.z * hsh[q*4+2] + v.w * hsh[q*4+3];
            }
        }
        float m = a;
        #pragma unroll
        for (int o = 16; o > 0; o >>= 1) m = fmaxf(m, __shfl_xor_sync(0xffffffffu, m, o));
        if (lane == 0) wred[wrp] = m;
        __syncthreads();
        float mx = wred[0];
        #pragma unroll
        for (int i = 1; i < 16; i++) mx = fmaxf(mx, wred[i]);

        float e = __expf(a - mx);
        sc[tid] = e;
        float s = e;
        #pragma unroll
        for (int o = 16; o > 0; o >>= 1) s += __shfl_xor_sync(0xffffffffu, s, o);
        __syncthreads();
        if (lane == 0) wred[wrp] = s;
        __syncthreads();
        float tot = 0.f;
        #pragma unroll
        for (int i = 0; i < 16; i++) tot += wred[i];
        float inv = 1.f / tot;

        float4 cacc = make_float4(0.f, 0.f, 0.f, 0.f);
        {
            const int sbase = wrp * 32;
            #pragma unroll 4
            for (int s2 = sbase; s2 < sbase + 32; s2++) {
                float4 v = *(const float4*)(eb + (size_t)s2 * 128 + lane * 4);
                float w4 = sc[s2];
                cacc.x += w4 * v.x; cacc.y += w4 * v.y;
                cacc.z += w4 * v.z; cacc.w += w4 * v.w;
            }
        }
        *(float4*)&red[wrp][lane * 4] = cacc;
        __syncthreads();
        if (tid < 128) {
            float c = 0.f;
            #pragma unroll
            for (int w2 = 0; w2 < 16; w2++) c += red[w2][tid];
            xe[tid] = c * inv;
        } else if (tid < 128 + Eq) {
            int d = tid - 128;
            int wrd = targets[b * Tq + step];
            xe[128 + d] = emb[(size_t)wrd * Eq + d];
        }
        __syncthreads();

        #pragma unroll 2
        for (int i = 0; i < 24; i++) {
            const int row = wrp * 24 + i;
            const float* wi = Wihd + (size_t)row * XD;
            const float* wh = Whhd + (size_t)row * 128;
            float ai = 0.f, cc = 0.f;
            #pragma unroll
            for (int q = 0; q < 5; q++) ai += wi[lane + q * 32] * xe[lane + q * 32];
            #pragma unroll
            for (int q = 0; q < 4; q++) cc += wh[lane + q * 32] * hsh[lane + q * 32];
            #pragma unroll
            for (int o = 16; o > 0; o >>= 1) {
                ai += __shfl_down_sync(0xffffffffu, ai, o);
                cc += __shfl_down_sync(0xffffffffu, cc, o);
            }
            if (lane == 0) { gis[row] = ai; ghs[row] = cc; }
        }
        __syncthreads();

        if (tid < 128) {
            float gi0 = gis[tid]       + bihd[tid];
            float gh0 = ghs[tid]       + bhhd[tid];
            float gi1 = gis[128 + tid] + bihd[128 + tid];
            float gh1 = ghs[128 + tid] + bhhd[128 + tid];
            float gi2 = gis[256 + tid] + bihd[256 + tid];
            float gh2 = ghs[256 + tid] + bhhd[256 + tid];
            float r = sigf(gi0 + gh0);
            float z = sigf(gi1 + gh1);
            float n = tanhf(gi2 + r * gh2);
            float hn = (1.f - z) * n + z * hsh[tid];
            hsh[tid] = hn;
            size_t idx = ((size_t)step * Bq + b) * Hq + tid;
            __nv_bfloat16 h1 = __float2bfloat16(hn);
            g_H1b[idx] = h1;
            g_H2b[idx] = __float2bfloat16(hn - __bfloat162float(h1));
        }
        __syncthreads();
    }
}

// ====== K5b: bf16x2 split of Wout ========================================
__global__ __launch_bounds__(256) void k_split_w(const float* __restrict__ Wout)
{
    size_t i = (size_t)blockIdx.x * 256 + threadIdx.x;
    if (i < (size_t)Vq * Hq) {
        float x = Wout[i];
        __nv_bfloat16 h1 = __float2bfloat16(x);
        g_W1b[i] = h1;
        g_W2b[i] = __float2bfloat16(x - __bfloat162float(h1));
    }
}

// ====== K6: logits via bf16x2-split mma.sync m16n8k16 =====================
// C = H @ Wout^T, 128x128x128 per CTA; grid (250 n-tiles, 15 steps)
// 8 warps in 2(m) x 4(n); each warp: 4 mt x 4 nt tiles of 16x8.
#define LROW 136                              // bf16 row stride (4*gr+tg banks)
#define HTILE (128 * LROW)
#define SMEM_MM (4 * HTILE * 2)               // 4 bf16 tiles = 139264 B
__global__ __launch_bounds__(256) void k_logits_bmma(
    const float* __restrict__ bout, float* __restrict__ out)
{
    extern __shared__ char smem[];
    __nv_bfloat16* Hs1 = (__nv_bfloat16*)smem;
    __nv_bfloat16* Hs2 = Hs1 + HTILE;
    __nv_bfloat16* Ws1 = Hs2 + HTILE;
    __nv_bfloat16* Ws2 = Ws1 + HTILE;

    const int tid = threadIdx.x;
    const int lane = tid & 31, wrp = tid >> 5;
    const int wm = wrp & 1, wn = wrp >> 1;
    const int gr = lane >> 2, tg = lane & 3;
    const int step = blockIdx.y;
    const int m0 = step * 128;
    const int n0 = blockIdx.x * 128;

    // load 4 bf16 tiles (each row = 128 bf16 = 16 x uint4)
    #pragma unroll
    for (int j = 0; j < 8; j++) {
        int fid = tid + j * 256;
        int row = fid >> 4, c = fid & 15;
        *(uint4*)&Hs1[row * LROW + c * 8] = ((const uint4*)&g_H1b[(size_t)(m0 + row) * Hq])[c];
        *(uint4*)&Hs2[row * LROW + c * 8] = ((const uint4*)&g_H2b[(size_t)(m0 + row) * Hq])[c];
        *(uint4*)&Ws1[row * LROW + c * 8] = ((const uint4*)&g_W1b[(size_t)(n0 + row) * Hq])[c];
        *(uint4*)&Ws2[row * LROW + c * 8] = ((const uint4*)&g_W2b[(size_t)(n0 + row) * Hq])[c];
    }
    __syncthreads();

    float acc[4][4][4];
    #pragma unroll
    for (int i = 0; i < 4; i++)
        #pragma unroll
        for (int j = 0; j < 4; j++)
            #pragma unroll
            for (int q = 0; q < 4; q++) acc[i][j][q] = 0.f;

    #pragma unroll
    for (int kk = 0; kk < 128; kk += 16) {
        uint32_t bh[4][2], bl[4][2];
        #pragma unroll
        for (int nt = 0; nt < 4; nt++) {
            int nr = (wn * 32 + nt * 8 + gr) * LROW + kk + 2 * tg;
            bh[nt][0] = *(const uint32_t*)&Ws1[nr];
            bh[nt][1] = *(const uint32_t*)&Ws1[nr + 8];
            bl[nt][0] = *(const uint32_t*)&Ws2[nr];
            bl[nt][1] = *(const uint32_t*)&Ws2[nr + 8];
        }
        #pragma unroll
        for (int mt = 0; mt < 4; mt++) {
            int mr = (wm * 64 + mt * 16 + gr) * LROW + kk + 2 * tg;
            uint32_t ah0 = *(const uint32_t*)&Hs1[mr];
            uint32_t ah1 = *(const uint32_t*)&Hs1[mr + 8 * LROW];
            uint32_t ah2 = *(const uint32_t*)&Hs1[mr + 8];
            uint32_t ah3 = *(const uint32_t*)&Hs1[mr + 8 * LROW + 8];
            uint32_t al0 = *(const uint32_t*)&Hs2[mr];
            uint32_t al1 = *(const uint32_t*)&Hs2[mr + 8 * LROW];
            uint32_t al2 = *(const uint32_t*)&Hs2[mr + 8];
            uint32_t al3 = *(const uint32_t*)&Hs2[mr + 8 * LROW + 8];
            #pragma unroll
            for (int nt = 0; nt < 4; nt++) {
                MMA_BF16(acc[mt][nt], ah0, ah1, ah2, ah3, bh[nt][0], bh[nt][1]);
                MMA_BF16(acc[mt][nt], ah0, ah1, ah2, ah3, bl[nt][0], bl[nt][1]);
                MMA_BF16(acc[mt][nt], al0, al1, al2, al3, bh[nt][0], bh[nt][1]);
            }
        }
    }
    __syncthreads();

    // stage through smem for coalesced output
    float* Ds = (float*)smem;                 // [128][132]
    #pragma unroll
    for (int mt = 0; mt < 4; mt++) {
        int r0 = wm * 64 + mt * 16 + gr;
        #pragma unroll
        for (int nt = 0; nt < 4; nt++) {
            int c0 = wn * 32 + nt * 8 + 2 * tg;
            Ds[r0 * 132 + c0]           = acc[mt][nt][0];
            Ds[r0 * 132 + c0 + 1]       = acc[mt][nt][1];
            Ds[(r0 + 8) * 132 + c0]     = acc[mt][nt][2];
            Ds[(r0 + 8) * 132 + c0 + 1] = acc[mt][nt][3];
        }
    }
    __syncthreads();

    const int c4 = (tid & 31) * 4;
    float4 bo = *(const float4*)&bout[n0 + c4];
    #pragma unroll
    for (int it = 0; it < 16; it++) {
        int r = (tid >> 5) + it * 8;          // r = b
        float4 v = *(const float4*)&Ds[r * 132 + c4];
        v.x += bo.x; v.y += bo.y; v.z += bo.z; v.w += bo.w;
        *(float4*)&out[((size_t)r * NSTEP + step) * Vq + n0 + c4] = v;
    }
}

// ============ trap sentinel (should never fire now) =======================
__global__ void k_trap() { __trap(); }

// ============================== launcher ==================================
extern "C" void kernel_launch(void* const* d_in, const int* in_sizes, int n_in,
                              void* d_out, int out_size)
{
    static const int SZ[21] = {65536, 2048, 1024000, 6144, 12288, 192, 192,
                               6144, 12288, 192, 192, 16384, 128, 16384, 128,
                               61440, 49152, 384, 384, 4096000, 32000};
    bool ok = (n_in == 21);
    if (ok) for (int i = 0; i < 21; i++) if (in_sizes[i] != SZ[i]) { ok = false; break; }
    if (!ok) { k_trap<<<1, 1>>>(); return; }

    const int*   inputs  = (const int*)  d_in[0];
    const int*   targets = (const int*)  d_in[1];
    const float* emb     = (const float*)d_in[2];
    const float* W_ih_f  = (const float*)d_in[3];
    const float* W_hh_f  = (const float*)d_in[4];
    const float* b_ih_f  = (const float*)d_in[5];
    const float* b_hh_f  = (const float*)d_in[6];
    const float* W_ih_b  = (const float*)d_in[7];
    const float* W_hh_b  = (const float*)d_in[8];
    const float* b_ih_b  = (const float*)d_in[9];
    const float* b_hh_b  = (const float*)d_in[10];
    const float* W1      = (const float*)d_in[11];
    const float* b1      = (const float*)d_in[12];
    const float* W2      = (const float*)d_in[13];
    const float* b2      = (const float*)d_in[14];
    const float* W_ih_d  = (const float*)d_in[15];
    const float* W_hh_d  = (const float*)d_in[16];
    const float* b_ih_d  = (const float*)d_in[17];
    const float* b_hh_d  = (const float*)d_in[18];
    const float* W_out   = (const float*)d_in[19];
    const float* b_out   = (const float*)d_in[20];
    float* out = (float*)d_out;

    cudaFuncSetAttribute(k_logits_bmma,
                         cudaFuncAttributeMaxDynamicSharedMemorySize, SMEM_MM);

    k_split_w<<<(Vq * Hq + 255) / 256, 256>>>(W_out);
    k_gi  <<<dim3(3, 512), 256>>>(inputs, emb, W_ih_f, W_ih_b, b_ih_f, b_ih_b);
    k_enc <<<256, 192>>>(W_hh_f, W_hh_b, b_hh_f, b_hh_b);
    k_c2  <<<128, 128>>>(W2, b1, b2);
    k_gate<<<dim3(1, 512), 256>>>(W1);
    k_dec_all<<<128, 512>>>(emb, targets, W_ih_d, W_hh_d, b_ih_d, b_hh_d);
    k_logits_bmma<<<dim3(250, 15), 256, SMEM_MM>>>(b_out, out);
}